// round 11
// baseline (speedup 1.0000x reference)
#include <cuda_runtime.h>
#include <cuda_fp16.h>
#include <stdint.h>
#include <math.h>

static constexpr int Bc = 2;
static constexpr int Nc = 16384;
static constexpr int Kc = 16;

// ---------------- scratch ----------------
__device__ __half g_fT[(size_t)Bc * Nc * 128];   // features transposed [b][n][c]
__device__ __half g_wh[311296];                  // all conv weights as fp16
__device__ __half g_x1[(size_t)Bc * Nc * 128];   // mlp1 out  [b][n][c]
__device__ __half g_m1[(size_t)Bc * Nc * 256];   // lse1 pooled mean
__device__ __half g_p1[(size_t)Bc * Nc * 128];   // pool1 pre-GN
__device__ __half g_m2[(size_t)Bc * Nc * 256];   // lse2 pooled mean
__device__ __half g_p2[(size_t)Bc * Nc * 256];   // pool2 pre-GN
__device__ __half g_x3[(size_t)Bc * Nc * 256];   // pool2 out
__device__ __half g_scp[(size_t)Bc * Nc * 512];  // shortcut pre-GN, [b][o][n] fp16

__device__ double g_geoS[Bc * 10];
__device__ double g_geoG[Bc * 55];
__device__ float g_p1s[Bc * 16], g_p1q[Bc * 16];
__device__ float g_p2s[Bc * 16], g_p2q[Bc * 16];
__device__ float g_scs[Bc * 16], g_scq[Bc * 16];

// weight blob offsets (in halves)
static constexpr int WOFF_W1 = 0;
static constexpr int WOFF_P1 = 16384;
static constexpr int WOFF_P2 = 49152;
static constexpr int WOFF_SC = 114688;
static constexpr int WOFF_M2 = 180224;
static constexpr int WTOT = 311296;

// ---------------- helpers ----------------
__device__ __forceinline__ uint32_t smem_u32(const void* p) {
    uint32_t a;
    asm("{ .reg .u64 t; cvta.to.shared.u64 t, %1; cvt.u32.u64 %0, t; }" : "=r"(a) : "l"(p));
    return a;
}
__device__ __forceinline__ void cpa16(uint32_t dst, const void* src) {
    asm volatile("cp.async.cg.shared.global [%0], [%1], 16;" :: "r"(dst), "l"(src));
}
#define CP_COMMIT() asm volatile("cp.async.commit_group;" ::: "memory")
#define CP_WAIT1() asm volatile("cp.async.wait_group 1;" ::: "memory")
#define CP_WAIT0() asm volatile("cp.async.wait_group 0;" ::: "memory")

#define MMA_F16(d, a, b) \
    asm volatile("mma.sync.aligned.m16n8k16.row.col.f32.f16.f16.f32 " \
        "{%0,%1,%2,%3}, {%4,%5,%6,%7}, {%8,%9}, {%0,%1,%2,%3};" \
        : "+f"((d)[0]), "+f"((d)[1]), "+f"((d)[2]), "+f"((d)[3]) \
        : "r"((a)[0]), "r"((a)[1]), "r"((a)[2]), "r"((a)[3]), \
          "r"((b)[0]), "r"((b)[1]))

#define LDSM4(r, addr) \
    asm volatile("ldmatrix.sync.aligned.m8n8.x4.shared.b16 {%0,%1,%2,%3}, [%4];" \
        : "=r"((r)[0]), "=r"((r)[1]), "=r"((r)[2]), "=r"((r)[3]) : "r"(addr))

// swizzled offset within a row-major 128B-row tile: row r, 16B-chunk c (0..7)
__device__ __forceinline__ uint32_t swoff(int r, int c) {
    return (uint32_t)(r * 128 + ((c ^ (r & 7)) << 4));
}

enum { EPI_LEAKY02 = 0, EPI_STATS = 1, EPI_TRANS_STATS = 2, EPI_FINAL = 3 };
static constexpr int CONV_SMEM = 3 * 32768 + 256;
static constexpr int OSH_STRIDE = 136;

// ---------------- K1: zero stats + convert weights + transpose -------------
__global__ __launch_bounds__(256) void prep_transpose_kernel(
    const float* __restrict__ w1, const float* __restrict__ pw1,
    const float* __restrict__ pw2, const float* __restrict__ scw,
    const float* __restrict__ mw,
    const float* __restrict__ features, __half* __restrict__ fT)
{
    __shared__ float t[32][33];
    int bid = blockIdx.x;
    if (bid < 4096) {
        int b = bid >> 11;
        int rem = bid & 2047;
        int cB = (rem >> 9) * 32, nB = (rem & 511) * 32;
        int tx = threadIdx.x & 31, ty = threadIdx.x >> 5;
#pragma unroll
        for (int i = 0; i < 4; ++i)
            t[ty + 8 * i][tx] =
                features[((size_t)b * 128 + cB + ty + 8 * i) * Nc + nB + tx];
        __syncthreads();
#pragma unroll
        for (int i = 0; i < 4; ++i)
            fT[((size_t)b * Nc + nB + ty + 8 * i) * 128 + cB + tx] =
                __float2half(t[tx][ty + 8 * i]);
    } else {
        int cb = bid - 4096;  // 0..255
        if (cb == 0) {
            int tt = threadIdx.x;
            if (tt < Bc * 10) g_geoS[tt] = 0.0;
            if (tt < Bc * 55) g_geoG[tt] = 0.0;
            if (tt < Bc * 16) {
                g_p1s[tt] = 0.f; g_p1q[tt] = 0.f;
                g_p2s[tt] = 0.f; g_p2q[tt] = 0.f;
                g_scs[tt] = 0.f; g_scq[tt] = 0.f;
            }
        }
        for (int i = cb * 256 + threadIdx.x; i < WTOT; i += 256 * 256) {
            float v;
            if (i < WOFF_P1) v = w1[i];
            else if (i < WOFF_P2) v = pw1[i - WOFF_P1];
            else if (i < WOFF_SC) v = pw2[i - WOFF_P2];
            else if (i < WOFF_M2) v = scw[i - WOFF_SC];
            else v = mw[i - WOFF_M2];
            g_wh[i] = __float2half(v);
        }
    }
}

// ---------------- geo moments (device body) ----------------
__device__ void geo_body(const float* __restrict__ coords,
                         const int* __restrict__ knn_idx,
                         const float* __restrict__ knn_dist, int bx, int b)
{
    const float* cb = coords + (size_t)b * Nc * 3;
    float S[10];
    float G[55];
#pragma unroll
    for (int c = 0; c < 10; c++) S[c] = 0.f;
#pragma unroll
    for (int p = 0; p < 55; p++) G[p] = 0.f;

    for (int it = bx * 256 + threadIdx.x; it < Nc * Kc; it += 64 * 256) {
        int n = it >> 4;
        size_t base = ((size_t)b * Nc + n) * Kc + (it & 15);
        float cx = cb[n * 3 + 0], cy = cb[n * 3 + 1], cz = cb[n * 3 + 2];
        int j = knn_idx[base];
        float nx = cb[j * 3 + 0], ny = cb[j * 3 + 1], nz = cb[j * 3 + 2];
        float dd = knn_dist[base];
        float g[10] = {cx, cy, cz, nx, ny, nz, cx - nx, cy - ny, cz - nz, dd};
        int p = 0;
#pragma unroll
        for (int c = 0; c < 10; c++) {
            S[c] += g[c];
#pragma unroll
            for (int d = c; d < 10; d++) G[p++] += g[c] * g[d];
        }
    }
#pragma unroll
    for (int c = 0; c < 10; c++)
        for (int off = 16; off; off >>= 1) S[c] += __shfl_xor_sync(~0u, S[c], off);
#pragma unroll
    for (int p = 0; p < 55; p++)
        for (int off = 16; off; off >>= 1) G[p] += __shfl_xor_sync(~0u, G[p], off);
    if ((threadIdx.x & 31) == 0) {
        for (int c = 0; c < 10; c++) atomicAdd(&g_geoS[b * 10 + c], (double)S[c]);
        for (int p = 0; p < 55; p++) atomicAdd(&g_geoG[b * 55 + p], (double)G[p]);
    }
}

// ---------------- conv device body: 128n x 128o tile, 64-col K chunks ------
template <int O, int C, int EPI, int GSIZE>
__device__ __forceinline__ void conv_dev(
    char* smem, int n0, int o0, int b,
    const __half* __restrict__ Wh, const float* __restrict__ bias,
    const __half* __restrict__ in, void* __restrict__ outv,
    const __half* __restrict__ scpre,
    const float* __restrict__ scgw, const float* __restrict__ scgb,
    float* gsum, float* gsq)
{
    const uint32_t sb = smem_u32(smem);
    float* ssh = (float*)(smem + 98304);
    float* sqh = ssh + 16;
    float* osf = (float*)smem;
    __half* osh = (__half*)smem;

    const int tid = threadIdx.x;
    const int w = tid >> 5, lane = tid & 31;
    const int wr = w & 1, wc = w >> 1;
    const int t = lane & 3, g = lane >> 2;

    const __half* xbase = in + ((size_t)b * Nc + n0) * C;
    const __half* wbase = Wh + (size_t)o0 * C;

    uint32_t sOff[4];
    const __half* gxp[4];
    const __half* gwp[4];
#pragma unroll
    for (int i = 0; i < 4; ++i) {
        int id = tid + 256 * i;
        int r = id >> 3, c = id & 7;
        sOff[i] = swoff(r, c);
        gxp[i] = xbase + (size_t)r * C + c * 8;
        gwp[i] = wbase + (size_t)r * C + c * 8;
    }

    const int quad = lane >> 3, lr = lane & 7;
    const int raA = (quad & 1) * 8 + lr, caA = quad >> 1;
    const int raB = (quad >> 1) * 8 + lr, caB = quad & 1;
    uint32_t rbA[4], rxA[4];
#pragma unroll
    for (int mi = 0; mi < 4; ++mi) {
        int row = wr * 64 + mi * 16 + raA;
        rbA[mi] = (uint32_t)(row * 128);
        rxA[mi] = (uint32_t)(row & 7);
    }
    uint32_t rbB[2], rxB[2];
#pragma unroll
    for (int oi = 0; oi < 2; ++oi) {
        int row = wc * 32 + oi * 16 + raB;
        rbB[oi] = 16384u + (uint32_t)(row * 128);
        rxB[oi] = (uint32_t)(row & 7);
    }

    float d[4][4][4];
#pragma unroll
    for (int mi = 0; mi < 4; ++mi)
#pragma unroll
        for (int ni = 0; ni < 4; ++ni)
#pragma unroll
            for (int e = 0; e < 4; ++e) d[mi][ni][e] = 0.f;

    constexpr int NCH = C / 64;
    auto stage = [&](int j) {
        uint32_t base = sb + (uint32_t)(j % 3) * 32768u;
        int cc = j * 64;
#pragma unroll
        for (int i = 0; i < 4; ++i) {
            cpa16(base + sOff[i], gxp[i] + cc);
            cpa16(base + 16384 + sOff[i], gwp[i] + cc);
        }
        CP_COMMIT();
    };
    stage(0);
    if (NCH > 1) stage(1);

    for (int j = 0; j < NCH; ++j) {
        if (j + 1 < NCH) CP_WAIT1(); else CP_WAIT0();
        __syncthreads();
        if (j + 2 < NCH) stage(j + 2);
        const uint32_t base = sb + (uint32_t)(j % 3) * 32768u;
#pragma unroll
        for (int kt = 0; kt < 4; ++kt) {
            uint32_t a[4][4], bb[2][4];
#pragma unroll
            for (int mi = 0; mi < 4; ++mi) {
                uint32_t cA = (uint32_t)(kt * 2 + caA) ^ rxA[mi];
                LDSM4(a[mi], base + rbA[mi] + (cA << 4));
            }
#pragma unroll
            for (int oi = 0; oi < 2; ++oi) {
                uint32_t cB = (uint32_t)(kt * 2 + caB) ^ rxB[oi];
                LDSM4(bb[oi], base + rbB[oi] + (cB << 4));
            }
#pragma unroll
            for (int mi = 0; mi < 4; ++mi)
#pragma unroll
                for (int ni = 0; ni < 4; ++ni) {
                    uint32_t bf[2] = {bb[ni >> 1][(ni & 1) * 2],
                                      bb[ni >> 1][(ni & 1) * 2 + 1]};
                    MMA_F16(d[mi][ni], a[mi], bf);
                }
        }
    }

    // ================= epilogues =================
    if constexpr (EPI == EPI_LEAKY02 || EPI == EPI_STATS) {
        __half* out = (__half*)outv;
        __syncthreads();
        if constexpr (EPI == EPI_STATS) {
            if (tid < 16) { ssh[tid] = 0.f; sqh[tid] = 0.f; }
            __syncthreads();
        }
        float js[4] = {0.f, 0.f, 0.f, 0.f}, jq[4] = {0.f, 0.f, 0.f, 0.f};
#pragma unroll
        for (int mi = 0; mi < 4; ++mi) {
            int p = wr * 64 + mi * 16 + g;
#pragma unroll
            for (int ni = 0; ni < 4; ++ni) {
                int ch = wc * 32 + ni * 8 + 2 * t;
                float b0 = bias[o0 + ch], b1 = bias[o0 + ch + 1];
                float v00 = d[mi][ni][0] + b0, v01 = d[mi][ni][1] + b1;
                float v10 = d[mi][ni][2] + b0, v11 = d[mi][ni][3] + b1;
                if constexpr (EPI == EPI_LEAKY02) {
                    v00 = v00 > 0.f ? v00 : 0.2f * v00;
                    v01 = v01 > 0.f ? v01 : 0.2f * v01;
                    v10 = v10 > 0.f ? v10 : 0.2f * v10;
                    v11 = v11 > 0.f ? v11 : 0.2f * v11;
                } else {
                    js[ni] += v00 + v01 + v10 + v11;
                    jq[ni] += v00 * v00 + v01 * v01 + v10 * v10 + v11 * v11;
                }
                *(__half2*)&osh[p * OSH_STRIDE + ch] = __floats2half2_rn(v00, v01);
                *(__half2*)&osh[(p + 8) * OSH_STRIDE + ch] = __floats2half2_rn(v10, v11);
            }
        }
        if constexpr (EPI == EPI_STATS) {
#pragma unroll
            for (int ni = 0; ni < 4; ++ni) {
                int gl = (wc * 32 + ni * 8) / GSIZE;
                atomicAdd(&ssh[gl], js[ni]);
                atomicAdd(&sqh[gl], jq[ni]);
            }
        }
        __syncthreads();
#pragma unroll
        for (int i = 0; i < 8; ++i) {
            int id = tid + 256 * i;
            int row = id >> 4, c16 = id & 15;
            uint4 v = *(uint4*)&osh[row * OSH_STRIDE + c16 * 8];
            *(uint4*)&out[((size_t)b * Nc + n0 + row) * O + o0 + c16 * 8] = v;
        }
        if constexpr (EPI == EPI_STATS) {
            constexpr int NG = 128 / GSIZE;
            if (tid < NG) {
                atomicAdd(&gsum[b * 16 + o0 / GSIZE + tid], ssh[tid]);
                atomicAdd(&gsq[b * 16 + o0 / GSIZE + tid], sqh[tid]);
            }
        }
    } else {
        __syncthreads();
        if (tid < 16) { ssh[tid] = 0.f; sqh[tid] = 0.f; }
        __syncthreads();
#pragma unroll
        for (int p = 0; p < 2; ++p) {
            if ((wc >> 1) == p) {
                float js[4] = {0.f, 0.f, 0.f, 0.f}, jq[4] = {0.f, 0.f, 0.f, 0.f};
#pragma unroll
                for (int mi = 0; mi < 4; ++mi) {
                    int nr = wr * 64 + mi * 16 + g;
#pragma unroll
                    for (int ni = 0; ni < 4; ++ni) {
                        int oc = (wc & 1) * 32 + ni * 8 + 2 * t;
                        float b0 = 0.f, b1 = 0.f;
                        if constexpr (EPI == EPI_TRANS_STATS) {
                            b0 = bias[o0 + p * 64 + oc];
                            b1 = bias[o0 + p * 64 + oc + 1];
                        }
                        float v00 = d[mi][ni][0] + b0, v01 = d[mi][ni][1] + b1;
                        float v10 = d[mi][ni][2] + b0, v11 = d[mi][ni][3] + b1;
                        if constexpr (EPI == EPI_TRANS_STATS) {
                            js[ni] += v00 + v01 + v10 + v11;
                            jq[ni] += v00 * v00 + v01 * v01 + v10 * v10 + v11 * v11;
                        }
                        osf[oc * 132 + nr] = v00;
                        osf[(oc + 1) * 132 + nr] = v01;
                        osf[oc * 132 + nr + 8] = v10;
                        osf[(oc + 1) * 132 + nr + 8] = v11;
                    }
                }
                if constexpr (EPI == EPI_TRANS_STATS) {
#pragma unroll
                    for (int ni = 0; ni < 4; ++ni) {
                        int gl = (p * 64 + (wc & 1) * 32 + ni * 8) / GSIZE;
                        atomicAdd(&ssh[gl], js[ni]);
                        atomicAdd(&sqh[gl], jq[ni]);
                    }
                }
            }
            __syncthreads();
#pragma unroll
            for (int rr = 0; rr < 8; ++rr) {
                int r = w + rr * 8;
                int og = o0 + p * 64 + r;
                float4 v = *(float4*)&osf[r * 132 + lane * 4];
                if constexpr (EPI == EPI_FINAL) {
                    float* op = (float*)outv + ((size_t)b * O + og) * Nc + n0;
                    float bi = bias[og];
                    const float Minv = 1.f / (GSIZE * (float)Nc);
                    int gg = og / GSIZE;
                    float mean = gsum[b * 16 + gg] * Minv;
                    float var = fmaxf(gsq[b * 16 + gg] * Minv - mean * mean, 0.f);
                    float rstd = rsqrtf(var + 1e-6f);
                    float av = rstd * scgw[og];
                    float cv = scgb[og] - mean * av;
                    uint2 sraw = *(const uint2*)(scpre +
                        ((size_t)b * O + og) * Nc + n0 + lane * 4);
                    float2 s0 = __half22float2(*(__half2*)&sraw.x);
                    float2 s1 = __half22float2(*(__half2*)&sraw.y);
                    float ss[4] = {s0.x, s0.y, s1.x, s1.y};
                    float4 rrv;
#pragma unroll
                    for (int e = 0; e < 4; ++e) {
                        float x = (&v.x)[e] + bi + fmaf(ss[e], av, cv);
                        (&rrv.x)[e] = x > 0.f ? x : 0.01f * x;
                    }
                    *(float4*)(op + lane * 4) = rrv;
                } else {
                    __half* op = (__half*)outv + ((size_t)b * O + og) * Nc + n0;
                    uint2 st;
                    *(__half2*)&st.x = __floats2half2_rn(v.x, v.y);
                    *(__half2*)&st.y = __floats2half2_rn(v.z, v.w);
                    *(uint2*)(op + lane * 4) = st;
                }
            }
            __syncthreads();
        }
        if constexpr (EPI == EPI_TRANS_STATS) {
            constexpr int NG = 128 / GSIZE;
            if (tid < NG) {
                atomicAdd(&gsum[b * 16 + o0 / GSIZE + tid], ssh[tid]);
                atomicAdd(&gsq[b * 16 + o0 / GSIZE + tid], sqh[tid]);
            }
        }
    }
}

// ---------------- standalone conv kernels ----------------------------------
template <int O, int C, int EPI, int GSIZE>
__global__ __launch_bounds__(256, 2) void mma_conv_k(
    const __half* __restrict__ Wh, const float* __restrict__ bias,
    const __half* __restrict__ in, void* __restrict__ outv,
    const __half* __restrict__ scpre,
    const float* __restrict__ scgw, const float* __restrict__ scgb,
    float* gsum, float* gsq)
{
    extern __shared__ __align__(16) char smem[];
    conv_dev<O, C, EPI, GSIZE>(smem, blockIdx.x * 128, blockIdx.y * 128,
                               blockIdx.z, Wh, bias, in, outv,
                               scpre, scgw, scgb, gsum, gsq);
}

// ---------------- K2: mlp1 + shortcut conv + geo moments -------------------
__global__ __launch_bounds__(256, 2) void fused_a_kernel(
    const __half* __restrict__ wh, const float* __restrict__ b1,
    const float* __restrict__ sc_b, const __half* __restrict__ fT,
    __half* __restrict__ x1, __half* __restrict__ scp,
    float* scs, float* scq,
    const float* __restrict__ coords, const int* __restrict__ knn_idx,
    const float* __restrict__ knn_dist)
{
    extern __shared__ __align__(16) char smem[];
    int y = blockIdx.y, b = blockIdx.z;
    if (y == 5) {
        if (blockIdx.x < 64) geo_body(coords, knn_idx, knn_dist, blockIdx.x, b);
        return;
    }
    if (y == 0)
        conv_dev<128, 128, EPI_LEAKY02, 8>(smem, blockIdx.x * 128, 0, b,
            wh + WOFF_W1, b1, fT, x1, nullptr, nullptr, nullptr, nullptr, nullptr);
    else
        conv_dev<512, 128, EPI_TRANS_STATS, 32>(smem, blockIdx.x * 128,
            (y - 1) * 128, b, wh + WOFF_SC, sc_b, fT, scp,
            nullptr, nullptr, nullptr, scs, scq);
}

// ---------------- normalize p2 -> x3 with inline fin2 ----------------------
__global__ __launch_bounds__(256) void normalize_h_kernel(
    const __half* __restrict__ p, __half* __restrict__ x,
    const float* __restrict__ sums, const float* __restrict__ sqs,
    const float* __restrict__ gw, const float* __restrict__ gb)
{
    size_t i = ((size_t)blockIdx.x * blockDim.x + threadIdx.x) * 4;
    int c = (int)(i % 256);
    int b = (int)(i / ((size_t)Nc * 256));
    const float Minv = 1.f / (16.f * Nc);
    int g = c >> 4;
    float mean = sums[b * 16 + g] * Minv;
    float var = fmaxf(sqs[b * 16 + g] * Minv - mean * mean, 0.f);
    float rstd = rsqrtf(var + 1e-6f);
    __half2 v0 = *(const __half2*)(p + i);
    __half2 v1 = *(const __half2*)(p + i + 2);
    float vv[4] = {__half2float(v0.x), __half2float(v0.y),
                   __half2float(v1.x), __half2float(v1.y)};
    float rr[4];
#pragma unroll
    for (int e = 0; e < 4; ++e) {
        float a = rstd * gw[c + e];
        float cc = gb[c + e] - mean * a;
        rr[e] = fmaxf(fmaf(vv[e], a, cc), 0.f);
    }
    *(__half2*)(x + i) = __floats2half2_rn(rr[0], rr[1]);
    *(__half2*)(x + i + 2) = __floats2half2_rn(rr[2], rr[3]);
}

// ---------------- fused LSE: inline GN-from-moments + float4 geo ------------
static constexpr int PTS = 8;
template <bool AFF>
__global__ __launch_bounds__(128) void lse_apply_kernel(
    const float* __restrict__ coords, const int* __restrict__ knn_idx,
    const float* __restrict__ knn_dist, const float* __restrict__ w,
    const float* __restrict__ lbias, const float* __restrict__ lgw,
    const float* __restrict__ lgb,
    const __half* __restrict__ xsrc, __half* __restrict__ mout,
    const float* __restrict__ sums, const float* __restrict__ sqs,
    const float* __restrict__ pgw, const float* __restrict__ pgb)
{
    __shared__ int sh_idx[PTS * 16];
    __shared__ float4 sh_g[PTS * 16];   // nbr.xyz, dist
    __shared__ float sh_ctr[PTS][3];
    __shared__ float2 spart[PTS][64];

    const int b = blockIdx.y;
    const int n0 = blockIdx.x * PTS;
    const int tid = threadIdx.x;
    const int lane = tid & 31;
    const float* cb = coords + (size_t)b * Nc * 3;

    float ddv;
    if (tid < PTS * 16) {
        size_t base = ((size_t)b * Nc + n0) * 16 + tid;
        sh_idx[tid] = knn_idx[base];
        ddv = knn_dist[base];
    }
    if (tid < PTS * 3) sh_ctr[tid / 3][tid % 3] = cb[n0 * 3 + tid];
    __syncthreads();
    if (tid < PTS * 16) {
        int j = sh_idx[tid];
        sh_g[tid] = make_float4(cb[j * 3 + 0], cb[j * 3 + 1], cb[j * 3 + 2], ddv);
    }
    // per-channel weights
    float wr[10];
#pragma unroll
    for (int c = 0; c < 10; c++) wr[c] = w[tid * 10 + c];
    const float wcx = wr[0] + wr[6], wcy = wr[1] + wr[7], wcz = wr[2] + wr[8];
    const float wnx = wr[3] - wr[6], wny = wr[4] - wr[7], wnz = wr[5] - wr[8];
    const float wd = wr[9];

    // inline closed-form GN affine from geo moments (fp32 from fp64 sums)
    float a, cc;
    {
        const float NK = (float)Nc * (float)Kc;
        float t1 = 0.f;
#pragma unroll
        for (int c = 0; c < 10; c++) t1 += wr[c] * (float)g_geoS[b * 10 + c];
        float t2 = 0.f;
        int p = 0;
#pragma unroll
        for (int c = 0; c < 10; c++)
#pragma unroll
            for (int dd = c; dd < 10; dd++) {
                float gv = (float)g_geoG[b * 55 + p]; p++;
                float ww = wr[c] * wr[dd];
                t2 += (c == dd ? ww : 2.f * ww) * gv;
            }
        float bo = lbias[tid];
        float sum = t1 + bo * NK;
        float sq = t2 + 2.f * bo * t1 + bo * bo * NK;
        // reduce over 8-channel GN group (consecutive tids within a warp)
#pragma unroll
        for (int off = 1; off < 8; off <<= 1) {
            sum += __shfl_xor_sync(~0u, sum, off);
            sq += __shfl_xor_sync(~0u, sq, off);
        }
        float M = 8.f * NK;
        float mean = sum / M;
        float var = fmaxf(sq / M - mean * mean, 0.f);
        float rstd = rsqrtf(var + 1e-6f);
        a = rstd * lgw[tid];
        cc = lgb[tid] + (bo - mean) * a;
    }

    // gather role: channel pair cp (2 channels), k-half h
    const int cp = tid & 63, h = tid >> 6;
    float an0 = 0.f, an1 = 0.f, cn0 = 0.f, cn1 = 0.f;
    if (AFF) {
        const float Minv = 1.f / (8.f * Nc);
        int ch0 = 2 * cp;
        int g = ch0 >> 3;
        float mean = sums[b * 16 + g] * Minv;
        float var = fmaxf(sqs[b * 16 + g] * Minv - mean * mean, 0.f);
        float rstd = rsqrtf(var + 1e-6f);
        an0 = rstd * pgw[ch0];
        cn0 = pgb[ch0] - mean * an0;
        an1 = rstd * pgw[ch0 + 1];
        cn1 = pgb[ch0 + 1] - mean * an1;
    }
    const __half* xb = xsrc + (size_t)b * Nc * 128;
    __syncthreads();

    float2 accn[PTS];
#pragma unroll
    for (int pi = 0; pi < PTS; pi++) {
        float cx = sh_ctr[pi][0], cy = sh_ctr[pi][1], cz = sh_ctr[pi][2];
        float dotc = wcx * cx + wcy * cy + wcz * cz;
        float accg = 0.f;
#pragma unroll
        for (int k = 0; k < 16; k++) {
            float4 gv = sh_g[pi * 16 + k];
            float dot = dotc + wnx * gv.x + wny * gv.y + wnz * gv.z + wd * gv.w;
            accg += fmaxf(fmaf(dot, a, cc), 0.f);
        }
        mout[((size_t)b * Nc + n0 + pi) * 256 + tid] = __float2half(accg * 0.0625f);

        float2 acc = make_float2(0.f, 0.f);
#pragma unroll
        for (int k = 0; k < 8; k++) {
            int s = pi * 16 + h * 8 + k;
            int j = sh_idx[s];
            float2 f = __half22float2(*(const __half2*)&xb[(size_t)j * 128 + 2 * cp]);
            if (AFF) {
                f.x = fmaxf(fmaf(f.x, an0, cn0), 0.f);
                f.y = fmaxf(fmaf(f.y, an1, cn1), 0.f);
            }
            acc.x += f.x; acc.y += f.y;
        }
        if (h == 1) spart[pi][cp] = acc;
        accn[pi] = acc;
    }
    __syncthreads();
    if (h == 0) {
#pragma unroll
        for (int pi = 0; pi < PTS; pi++) {
            float2 o = spart[pi][cp];
            o.x = (o.x + accn[pi].x) * 0.0625f;
            o.y = (o.y + accn[pi].y) * 0.0625f;
            *(__half2*)&mout[((size_t)b * Nc + n0 + pi) * 256 + 128 + 2 * cp] =
                __floats2half2_rn(o.x, o.y);
        }
    }
}

// ---------------- host ----------------
#define SYM(ty, p, s) do { void* _t; cudaGetSymbolAddress(&_t, s); p = (ty)_t; } while (0)

extern "C" void kernel_launch(void* const* d_in, const int* in_sizes, int n_in,
                              void* d_out, int out_size)
{
    (void)in_sizes; (void)n_in; (void)out_size;
    const float* coords   = (const float*)d_in[0];
    const float* features = (const float*)d_in[1];
    const float* knn_dist = (const float*)d_in[2];
    const int*   knn_idx  = (const int*)d_in[3];
    const float* w1       = (const float*)d_in[4];
    const float* b1       = (const float*)d_in[5];
    const float* lse1_w   = (const float*)d_in[6];
    const float* lse1_b   = (const float*)d_in[7];
    const float* lse1_gw  = (const float*)d_in[8];
    const float* lse1_gb  = (const float*)d_in[9];
    const float* pool1_w  = (const float*)d_in[10];
    const float* pool1_b  = (const float*)d_in[11];
    const float* pool1_gw = (const float*)d_in[12];
    const float* pool1_gb = (const float*)d_in[13];
    const float* lse2_w   = (const float*)d_in[14];
    const float* lse2_b   = (const float*)d_in[15];
    const float* lse2_gw  = (const float*)d_in[16];
    const float* lse2_gb  = (const float*)d_in[17];
    const float* pool2_w  = (const float*)d_in[18];
    const float* pool2_b  = (const float*)d_in[19];
    const float* pool2_gw = (const float*)d_in[20];
    const float* pool2_gb = (const float*)d_in[21];
    const float* mlp2_w   = (const float*)d_in[22];
    const float* mlp2_b   = (const float*)d_in[23];
    const float* sc_w     = (const float*)d_in[24];
    const float* sc_b     = (const float*)d_in[25];
    const float* sc_gw    = (const float*)d_in[26];
    const float* sc_gb    = (const float*)d_in[27];
    float* out = (float*)d_out;

    __half *fT, *wh, *x1, *m1, *p1, *m2, *p2, *x3, *scp;
    float *p1s, *p1q, *p2s, *p2q, *scs, *scq;
    SYM(__half*, fT, g_fT); SYM(__half*, wh, g_wh);
    SYM(__half*, x1, g_x1); SYM(__half*, m1, g_m1); SYM(__half*, p1, g_p1);
    SYM(__half*, m2, g_m2); SYM(__half*, p2, g_p2); SYM(__half*, x3, g_x3);
    SYM(__half*, scp, g_scp);
    SYM(float*, p1s, g_p1s); SYM(float*, p1q, g_p1q);
    SYM(float*, p2s, g_p2s); SYM(float*, p2q, g_p2q);
    SYM(float*, scs, g_scs); SYM(float*, scq, g_scq);

    cudaFuncSetAttribute(fused_a_kernel,
                         cudaFuncAttributeMaxDynamicSharedMemorySize, CONV_SMEM);
    cudaFuncSetAttribute(mma_conv_k<128, 256, EPI_STATS, 8>,
                         cudaFuncAttributeMaxDynamicSharedMemorySize, CONV_SMEM);
    cudaFuncSetAttribute(mma_conv_k<256, 256, EPI_STATS, 16>,
                         cudaFuncAttributeMaxDynamicSharedMemorySize, CONV_SMEM);
    cudaFuncSetAttribute(mma_conv_k<512, 256, EPI_FINAL, 32>,
                         cudaFuncAttributeMaxDynamicSharedMemorySize, CONV_SMEM);

    // K1: zero stats + weight convert + feature transpose
    prep_transpose_kernel<<<4096 + 256, 256>>>(w1, pool1_w, pool2_w, sc_w,
                                               mlp2_w, features, fT);
    // K2: mlp1 (y=0) + shortcut conv (y=1..4) + geo moments (y=5)
    fused_a_kernel<<<dim3(Nc / 128, 6, Bc), 256, CONV_SMEM>>>(
        wh, b1, sc_b, fT, x1, scp, scs, scq, coords, knn_idx, knn_dist);
    // K3: lse1 (inline GN-from-moments)
    lse_apply_kernel<false><<<dim3(Nc / PTS, Bc), 128>>>(
        coords, knn_idx, knn_dist, lse1_w, lse1_b, lse1_gw, lse1_gb, x1, m1,
        nullptr, nullptr, nullptr, nullptr);
    // K4: pool1 conv + stats
    mma_conv_k<128, 256, EPI_STATS, 8>
        <<<dim3(Nc / 128, 1, Bc), 256, CONV_SMEM>>>(wh + WOFF_P1, pool1_b, m1, p1,
                                                    nullptr, nullptr, nullptr,
                                                    p1s, p1q);
    // K5: lse2 (inline pool1 GN finalize + GN-from-moments)
    lse_apply_kernel<true><<<dim3(Nc / PTS, Bc), 128>>>(
        coords, knn_idx, knn_dist, lse2_w, lse2_b, lse2_gw, lse2_gb, p1, m2,
        p1s, p1q, pool1_gw, pool1_gb);
    // K6: pool2 conv + stats
    mma_conv_k<256, 256, EPI_STATS, 16>
        <<<dim3(Nc / 128, 2, Bc), 256, CONV_SMEM>>>(wh + WOFF_P2, pool2_b, m2, p2,
                                                    nullptr, nullptr, nullptr,
                                                    p2s, p2q);
    // K7: normalize (inline pool2 GN finalize)
    normalize_h_kernel<<<(Bc * Nc * 256) / 1024, 256>>>(p2, x3, p2s, p2q,
                                                        pool2_gw, pool2_gb);
    // K8: final conv + inline shortcut GN + leaky(0.01) -> out [b][o][n] fp32
    mma_conv_k<512, 256, EPI_FINAL, 32>
        <<<dim3(Nc / 128, 4, Bc), 256, CONV_SMEM>>>(wh + WOFF_M2, mlp2_b, x3, out,
                                                    scp, sc_gw, sc_gb, scs, scq);
}

// round 12
// speedup vs baseline: 1.1251x; 1.1251x over previous
#include <cuda_runtime.h>
#include <cuda_fp16.h>
#include <stdint.h>
#include <math.h>

static constexpr int Bc = 2;
static constexpr int Nc = 16384;
static constexpr int Kc = 16;

// ---------------- scratch ----------------
__device__ __half g_fT[(size_t)Bc * Nc * 128];   // features transposed [b][n][c]
__device__ __half g_wh[311296];                  // all conv weights as fp16
__device__ __half g_x1[(size_t)Bc * Nc * 128];   // mlp1 out  [b][n][c]
__device__ __half g_m1[(size_t)Bc * Nc * 256];   // lse1 pooled mean
__device__ __half g_p1[(size_t)Bc * Nc * 128];   // pool1 pre-GN
__device__ __half g_m2[(size_t)Bc * Nc * 256];   // lse2 pooled mean
__device__ __half g_p2[(size_t)Bc * Nc * 256];   // pool2 pre-GN
__device__ __half g_x3[(size_t)Bc * Nc * 256];   // pool2 out
__device__ __half g_scp[(size_t)Bc * Nc * 512];  // shortcut pre-GN, [b][o][n] fp16

__device__ double g_geoS[Bc * 10];
__device__ double g_geoG[Bc * 55];
__device__ float g_lse1a[Bc * 128], g_lse1c[Bc * 128];
__device__ float g_lse2a[Bc * 128], g_lse2c[Bc * 128];
__device__ float g_p1s[Bc * 16], g_p1q[Bc * 16];
__device__ float g_p2s[Bc * 16], g_p2q[Bc * 16];
__device__ float g_scs[Bc * 16], g_scq[Bc * 16];

// weight blob offsets (in halves)
static constexpr int WOFF_W1 = 0;
static constexpr int WOFF_P1 = 16384;
static constexpr int WOFF_P2 = 49152;
static constexpr int WOFF_SC = 114688;
static constexpr int WOFF_M2 = 180224;
static constexpr int WTOT = 311296;

// ---------------- helpers ----------------
__device__ __forceinline__ uint32_t smem_u32(const void* p) {
    uint32_t a;
    asm("{ .reg .u64 t; cvta.to.shared.u64 t, %1; cvt.u32.u64 %0, t; }" : "=r"(a) : "l"(p));
    return a;
}
__device__ __forceinline__ void cpa16(uint32_t dst, const void* src) {
    asm volatile("cp.async.cg.shared.global [%0], [%1], 16;" :: "r"(dst), "l"(src));
}
#define CP_COMMIT() asm volatile("cp.async.commit_group;" ::: "memory")
#define CP_WAIT1() asm volatile("cp.async.wait_group 1;" ::: "memory")
#define CP_WAIT0() asm volatile("cp.async.wait_group 0;" ::: "memory")

#define MMA_F16(d, a, b) \
    asm volatile("mma.sync.aligned.m16n8k16.row.col.f32.f16.f16.f32 " \
        "{%0,%1,%2,%3}, {%4,%5,%6,%7}, {%8,%9}, {%0,%1,%2,%3};" \
        : "+f"((d)[0]), "+f"((d)[1]), "+f"((d)[2]), "+f"((d)[3]) \
        : "r"((a)[0]), "r"((a)[1]), "r"((a)[2]), "r"((a)[3]), \
          "r"((b)[0]), "r"((b)[1]))

#define LDSM4(r, addr) \
    asm volatile("ldmatrix.sync.aligned.m8n8.x4.shared.b16 {%0,%1,%2,%3}, [%4];" \
        : "=r"((r)[0]), "=r"((r)[1]), "=r"((r)[2]), "=r"((r)[3]) : "r"(addr))

// swizzled offset within a row-major 128B-row tile: row r, 16B-chunk c (0..7)
__device__ __forceinline__ uint32_t swoff(int r, int c) {
    return (uint32_t)(r * 128 + ((c ^ (r & 7)) << 4));
}

enum { EPI_LEAKY02 = 0, EPI_STATS = 1, EPI_TRANS_STATS = 2, EPI_FINAL = 3 };
static constexpr int CONV_SMEM = 3 * 32768 + 256;
static constexpr int OSH_STRIDE = 136;

// ---------------- K1: zero stats + convert weights + transpose -------------
__global__ __launch_bounds__(256) void prep_transpose_kernel(
    const float* __restrict__ w1, const float* __restrict__ pw1,
    const float* __restrict__ pw2, const float* __restrict__ scw,
    const float* __restrict__ mw,
    const float* __restrict__ features, __half* __restrict__ fT)
{
    __shared__ float t[32][33];
    int bid = blockIdx.x;
    if (bid < 4096) {
        int b = bid >> 11;
        int rem = bid & 2047;
        int cB = (rem >> 9) * 32, nB = (rem & 511) * 32;
        int tx = threadIdx.x & 31, ty = threadIdx.x >> 5;
#pragma unroll
        for (int i = 0; i < 4; ++i)
            t[ty + 8 * i][tx] =
                features[((size_t)b * 128 + cB + ty + 8 * i) * Nc + nB + tx];
        __syncthreads();
#pragma unroll
        for (int i = 0; i < 4; ++i)
            fT[((size_t)b * Nc + nB + ty + 8 * i) * 128 + cB + tx] =
                __float2half(t[tx][ty + 8 * i]);
    } else {
        int cb = bid - 4096;  // 0..255
        if (cb == 0) {
            int tt = threadIdx.x;
            if (tt < Bc * 10) g_geoS[tt] = 0.0;
            if (tt < Bc * 55) g_geoG[tt] = 0.0;
            if (tt < Bc * 16) {
                g_p1s[tt] = 0.f; g_p1q[tt] = 0.f;
                g_p2s[tt] = 0.f; g_p2q[tt] = 0.f;
                g_scs[tt] = 0.f; g_scq[tt] = 0.f;
            }
        }
        for (int i = cb * 256 + threadIdx.x; i < WTOT; i += 256 * 256) {
            float v;
            if (i < WOFF_P1) v = w1[i];
            else if (i < WOFF_P2) v = pw1[i - WOFF_P1];
            else if (i < WOFF_SC) v = pw2[i - WOFF_P2];
            else if (i < WOFF_M2) v = scw[i - WOFF_SC];
            else v = mw[i - WOFF_M2];
            g_wh[i] = __float2half(v);
        }
    }
}

// ---------------- geo moments (device body) ----------------
__device__ void geo_body(const float* __restrict__ coords,
                         const int* __restrict__ knn_idx,
                         const float* __restrict__ knn_dist, int bx, int b)
{
    const float* cb = coords + (size_t)b * Nc * 3;
    float S[10];
    float G[55];
#pragma unroll
    for (int c = 0; c < 10; c++) S[c] = 0.f;
#pragma unroll
    for (int p = 0; p < 55; p++) G[p] = 0.f;

    for (int it = bx * 256 + threadIdx.x; it < Nc * Kc; it += 64 * 256) {
        int n = it >> 4;
        size_t base = ((size_t)b * Nc + n) * Kc + (it & 15);
        float cx = cb[n * 3 + 0], cy = cb[n * 3 + 1], cz = cb[n * 3 + 2];
        int j = knn_idx[base];
        float nx = cb[j * 3 + 0], ny = cb[j * 3 + 1], nz = cb[j * 3 + 2];
        float dd = knn_dist[base];
        float g[10] = {cx, cy, cz, nx, ny, nz, cx - nx, cy - ny, cz - nz, dd};
        int p = 0;
#pragma unroll
        for (int c = 0; c < 10; c++) {
            S[c] += g[c];
#pragma unroll
            for (int d = c; d < 10; d++) G[p++] += g[c] * g[d];
        }
    }
#pragma unroll
    for (int c = 0; c < 10; c++)
        for (int off = 16; off; off >>= 1) S[c] += __shfl_xor_sync(~0u, S[c], off);
#pragma unroll
    for (int p = 0; p < 55; p++)
        for (int off = 16; off; off >>= 1) G[p] += __shfl_xor_sync(~0u, G[p], off);
    if ((threadIdx.x & 31) == 0) {
        for (int c = 0; c < 10; c++) atomicAdd(&g_geoS[b * 10 + c], (double)S[c]);
        for (int p = 0; p < 55; p++) atomicAdd(&g_geoG[b * 55 + p], (double)G[p]);
    }
}

// ---------------- closed-form GN stats for BOTH LSE layers (fp32) ---------
__global__ void lse_finalize_kernel(
    const float* __restrict__ w1p, const float* __restrict__ b1p,
    const float* __restrict__ gw1, const float* __restrict__ gb1,
    const float* __restrict__ w2p, const float* __restrict__ b2p,
    const float* __restrict__ gw2, const float* __restrict__ gb2,
    float* __restrict__ a1o, float* __restrict__ c1o,
    float* __restrict__ a2o, float* __restrict__ c2o)
{
    int b = blockIdx.x;
    int layer = blockIdx.y;
    const float* w = layer ? w2p : w1p;
    const float* bias = layer ? b2p : b1p;
    const float* gw = layer ? gw2 : gw1;
    const float* gb = layer ? gb2 : gb1;
    float* aOut = layer ? a2o : a1o;
    float* cOut = layer ? c2o : c1o;

    __shared__ float sS[10], sG[55];
    int o = threadIdx.x;  // 128
    if (o < 10) sS[o] = (float)g_geoS[b * 10 + o];
    if (o < 55) sG[o] = (float)g_geoG[b * 55 + o];
    __syncthreads();

    float wr[10];
#pragma unroll
    for (int c = 0; c < 10; c++) wr[c] = w[o * 10 + c];
    float t1 = 0.f;
#pragma unroll
    for (int c = 0; c < 10; c++) t1 += wr[c] * sS[c];
    float t2 = 0.f;
    int p = 0;
#pragma unroll
    for (int c = 0; c < 10; c++)
#pragma unroll
        for (int d = c; d < 10; d++) {
            float ww = wr[c] * wr[d];
            t2 += (c == d ? ww : 2.f * ww) * sG[p];
            p++;
        }
    const float NK = (float)Nc * (float)Kc;
    float bo = bias[o];
    float sum = t1 + bo * NK;
    float sq = t2 + 2.f * bo * t1 + bo * bo * NK;
    // reduce over 8-channel GN group (consecutive lanes)
#pragma unroll
    for (int off = 1; off < 8; off <<= 1) {
        sum += __shfl_xor_sync(~0u, sum, off);
        sq += __shfl_xor_sync(~0u, sq, off);
    }
    float M = 8.f * NK;
    float mean = sum / M;
    float var = fmaxf(sq / M - mean * mean, 0.f);
    float rstd = rsqrtf(var + 1e-6f);
    float a = rstd * gw[o];
    aOut[b * 128 + o] = a;
    cOut[b * 128 + o] = gb[o] + (bo - mean) * a;
}

// ---------------- conv device body: 128n x 128o tile, 64-col K chunks ------
template <int O, int C, int EPI, int GSIZE>
__device__ __forceinline__ void conv_dev(
    char* smem, int n0, int o0, int b,
    const __half* __restrict__ Wh, const float* __restrict__ bias,
    const __half* __restrict__ in, void* __restrict__ outv,
    const __half* __restrict__ scpre,
    const float* __restrict__ scgw, const float* __restrict__ scgb,
    float* gsum, float* gsq)
{
    const uint32_t sb = smem_u32(smem);
    float* ssh = (float*)(smem + 98304);
    float* sqh = ssh + 16;
    float* osf = (float*)smem;
    __half* osh = (__half*)smem;

    const int tid = threadIdx.x;
    const int w = tid >> 5, lane = tid & 31;
    const int wr = w & 1, wc = w >> 1;
    const int t = lane & 3, g = lane >> 2;

    const __half* xbase = in + ((size_t)b * Nc + n0) * C;
    const __half* wbase = Wh + (size_t)o0 * C;

    uint32_t sOff[4];
    const __half* gxp[4];
    const __half* gwp[4];
#pragma unroll
    for (int i = 0; i < 4; ++i) {
        int id = tid + 256 * i;
        int r = id >> 3, c = id & 7;
        sOff[i] = swoff(r, c);
        gxp[i] = xbase + (size_t)r * C + c * 8;
        gwp[i] = wbase + (size_t)r * C + c * 8;
    }

    const int quad = lane >> 3, lr = lane & 7;
    const int raA = (quad & 1) * 8 + lr, caA = quad >> 1;
    const int raB = (quad >> 1) * 8 + lr, caB = quad & 1;
    uint32_t rbA[4], rxA[4];
#pragma unroll
    for (int mi = 0; mi < 4; ++mi) {
        int row = wr * 64 + mi * 16 + raA;
        rbA[mi] = (uint32_t)(row * 128);
        rxA[mi] = (uint32_t)(row & 7);
    }
    uint32_t rbB[2], rxB[2];
#pragma unroll
    for (int oi = 0; oi < 2; ++oi) {
        int row = wc * 32 + oi * 16 + raB;
        rbB[oi] = 16384u + (uint32_t)(row * 128);
        rxB[oi] = (uint32_t)(row & 7);
    }

    float d[4][4][4];
#pragma unroll
    for (int mi = 0; mi < 4; ++mi)
#pragma unroll
        for (int ni = 0; ni < 4; ++ni)
#pragma unroll
            for (int e = 0; e < 4; ++e) d[mi][ni][e] = 0.f;

    constexpr int NCH = C / 64;
    auto stage = [&](int j) {
        uint32_t base = sb + (uint32_t)(j % 3) * 32768u;
        int cc = j * 64;
#pragma unroll
        for (int i = 0; i < 4; ++i) {
            cpa16(base + sOff[i], gxp[i] + cc);
            cpa16(base + 16384 + sOff[i], gwp[i] + cc);
        }
        CP_COMMIT();
    };
    stage(0);
    if (NCH > 1) stage(1);

    for (int j = 0; j < NCH; ++j) {
        if (j + 1 < NCH) CP_WAIT1(); else CP_WAIT0();
        __syncthreads();
        if (j + 2 < NCH) stage(j + 2);
        const uint32_t base = sb + (uint32_t)(j % 3) * 32768u;
#pragma unroll
        for (int kt = 0; kt < 4; ++kt) {
            uint32_t a[4][4], bb[2][4];
#pragma unroll
            for (int mi = 0; mi < 4; ++mi) {
                uint32_t cA = (uint32_t)(kt * 2 + caA) ^ rxA[mi];
                LDSM4(a[mi], base + rbA[mi] + (cA << 4));
            }
#pragma unroll
            for (int oi = 0; oi < 2; ++oi) {
                uint32_t cB = (uint32_t)(kt * 2 + caB) ^ rxB[oi];
                LDSM4(bb[oi], base + rbB[oi] + (cB << 4));
            }
#pragma unroll
            for (int mi = 0; mi < 4; ++mi)
#pragma unroll
                for (int ni = 0; ni < 4; ++ni) {
                    uint32_t bf[2] = {bb[ni >> 1][(ni & 1) * 2],
                                      bb[ni >> 1][(ni & 1) * 2 + 1]};
                    MMA_F16(d[mi][ni], a[mi], bf);
                }
        }
    }

    // ================= epilogues =================
    if constexpr (EPI == EPI_LEAKY02 || EPI == EPI_STATS) {
        __half* out = (__half*)outv;
        __syncthreads();
        if constexpr (EPI == EPI_STATS) {
            if (tid < 16) { ssh[tid] = 0.f; sqh[tid] = 0.f; }
            __syncthreads();
        }
        float js[4] = {0.f, 0.f, 0.f, 0.f}, jq[4] = {0.f, 0.f, 0.f, 0.f};
#pragma unroll
        for (int mi = 0; mi < 4; ++mi) {
            int p = wr * 64 + mi * 16 + g;
#pragma unroll
            for (int ni = 0; ni < 4; ++ni) {
                int ch = wc * 32 + ni * 8 + 2 * t;
                float b0 = bias[o0 + ch], b1 = bias[o0 + ch + 1];
                float v00 = d[mi][ni][0] + b0, v01 = d[mi][ni][1] + b1;
                float v10 = d[mi][ni][2] + b0, v11 = d[mi][ni][3] + b1;
                if constexpr (EPI == EPI_LEAKY02) {
                    v00 = v00 > 0.f ? v00 : 0.2f * v00;
                    v01 = v01 > 0.f ? v01 : 0.2f * v01;
                    v10 = v10 > 0.f ? v10 : 0.2f * v10;
                    v11 = v11 > 0.f ? v11 : 0.2f * v11;
                } else {
                    js[ni] += v00 + v01 + v10 + v11;
                    jq[ni] += v00 * v00 + v01 * v01 + v10 * v10 + v11 * v11;
                }
                *(__half2*)&osh[p * OSH_STRIDE + ch] = __floats2half2_rn(v00, v01);
                *(__half2*)&osh[(p + 8) * OSH_STRIDE + ch] = __floats2half2_rn(v10, v11);
            }
        }
        if constexpr (EPI == EPI_STATS) {
#pragma unroll
            for (int ni = 0; ni < 4; ++ni) {
                int gl = (wc * 32 + ni * 8) / GSIZE;
                atomicAdd(&ssh[gl], js[ni]);
                atomicAdd(&sqh[gl], jq[ni]);
            }
        }
        __syncthreads();
#pragma unroll
        for (int i = 0; i < 8; ++i) {
            int id = tid + 256 * i;
            int row = id >> 4, c16 = id & 15;
            uint4 v = *(uint4*)&osh[row * OSH_STRIDE + c16 * 8];
            *(uint4*)&out[((size_t)b * Nc + n0 + row) * O + o0 + c16 * 8] = v;
        }
        if constexpr (EPI == EPI_STATS) {
            constexpr int NG = 128 / GSIZE;
            if (tid < NG) {
                atomicAdd(&gsum[b * 16 + o0 / GSIZE + tid], ssh[tid]);
                atomicAdd(&gsq[b * 16 + o0 / GSIZE + tid], sqh[tid]);
            }
        }
    } else {
        __syncthreads();
        if (tid < 16) { ssh[tid] = 0.f; sqh[tid] = 0.f; }
        __syncthreads();
#pragma unroll
        for (int p = 0; p < 2; ++p) {
            if ((wc >> 1) == p) {
                float js[4] = {0.f, 0.f, 0.f, 0.f}, jq[4] = {0.f, 0.f, 0.f, 0.f};
#pragma unroll
                for (int mi = 0; mi < 4; ++mi) {
                    int nr = wr * 64 + mi * 16 + g;
#pragma unroll
                    for (int ni = 0; ni < 4; ++ni) {
                        int oc = (wc & 1) * 32 + ni * 8 + 2 * t;
                        float b0 = 0.f, b1 = 0.f;
                        if constexpr (EPI == EPI_TRANS_STATS) {
                            b0 = bias[o0 + p * 64 + oc];
                            b1 = bias[o0 + p * 64 + oc + 1];
                        }
                        float v00 = d[mi][ni][0] + b0, v01 = d[mi][ni][1] + b1;
                        float v10 = d[mi][ni][2] + b0, v11 = d[mi][ni][3] + b1;
                        if constexpr (EPI == EPI_TRANS_STATS) {
                            js[ni] += v00 + v01 + v10 + v11;
                            jq[ni] += v00 * v00 + v01 * v01 + v10 * v10 + v11 * v11;
                        }
                        osf[oc * 132 + nr] = v00;
                        osf[(oc + 1) * 132 + nr] = v01;
                        osf[oc * 132 + nr + 8] = v10;
                        osf[(oc + 1) * 132 + nr + 8] = v11;
                    }
                }
                if constexpr (EPI == EPI_TRANS_STATS) {
#pragma unroll
                    for (int ni = 0; ni < 4; ++ni) {
                        int gl = (p * 64 + (wc & 1) * 32 + ni * 8) / GSIZE;
                        atomicAdd(&ssh[gl], js[ni]);
                        atomicAdd(&sqh[gl], jq[ni]);
                    }
                }
            }
            __syncthreads();
#pragma unroll
            for (int rr = 0; rr < 8; ++rr) {
                int r = w + rr * 8;
                int og = o0 + p * 64 + r;
                float4 v = *(float4*)&osf[r * 132 + lane * 4];
                if constexpr (EPI == EPI_FINAL) {
                    float* op = (float*)outv + ((size_t)b * O + og) * Nc + n0;
                    float bi = bias[og];
                    const float Minv = 1.f / (GSIZE * (float)Nc);
                    int gg = og / GSIZE;
                    float mean = gsum[b * 16 + gg] * Minv;
                    float var = fmaxf(gsq[b * 16 + gg] * Minv - mean * mean, 0.f);
                    float rstd = rsqrtf(var + 1e-6f);
                    float av = rstd * scgw[og];
                    float cv = scgb[og] - mean * av;
                    uint2 sraw = *(const uint2*)(scpre +
                        ((size_t)b * O + og) * Nc + n0 + lane * 4);
                    float2 s0 = __half22float2(*(__half2*)&sraw.x);
                    float2 s1 = __half22float2(*(__half2*)&sraw.y);
                    float ss[4] = {s0.x, s0.y, s1.x, s1.y};
                    float4 rrv;
#pragma unroll
                    for (int e = 0; e < 4; ++e) {
                        float x = (&v.x)[e] + bi + fmaf(ss[e], av, cv);
                        (&rrv.x)[e] = x > 0.f ? x : 0.01f * x;
                    }
                    *(float4*)(op + lane * 4) = rrv;
                } else {
                    __half* op = (__half*)outv + ((size_t)b * O + og) * Nc + n0;
                    uint2 st;
                    *(__half2*)&st.x = __floats2half2_rn(v.x, v.y);
                    *(__half2*)&st.y = __floats2half2_rn(v.z, v.w);
                    *(uint2*)(op + lane * 4) = st;
                }
            }
            __syncthreads();
        }
        if constexpr (EPI == EPI_TRANS_STATS) {
            constexpr int NG = 128 / GSIZE;
            if (tid < NG) {
                atomicAdd(&gsum[b * 16 + o0 / GSIZE + tid], ssh[tid]);
                atomicAdd(&gsq[b * 16 + o0 / GSIZE + tid], sqh[tid]);
            }
        }
    }
}

// ---------------- standalone conv kernels ----------------------------------
template <int O, int C, int EPI, int GSIZE>
__global__ __launch_bounds__(256, 2) void mma_conv_k(
    const __half* __restrict__ Wh, const float* __restrict__ bias,
    const __half* __restrict__ in, void* __restrict__ outv,
    const __half* __restrict__ scpre,
    const float* __restrict__ scgw, const float* __restrict__ scgb,
    float* gsum, float* gsq)
{
    extern __shared__ __align__(16) char smem[];
    conv_dev<O, C, EPI, GSIZE>(smem, blockIdx.x * 128, blockIdx.y * 128,
                               blockIdx.z, Wh, bias, in, outv,
                               scpre, scgw, scgb, gsum, gsq);
}

// ---------------- K2: mlp1 + shortcut conv + geo moments -------------------
__global__ __launch_bounds__(256, 2) void fused_a_kernel(
    const __half* __restrict__ wh, const float* __restrict__ b1,
    const float* __restrict__ sc_b, const __half* __restrict__ fT,
    __half* __restrict__ x1, __half* __restrict__ scp,
    float* scs, float* scq,
    const float* __restrict__ coords, const int* __restrict__ knn_idx,
    const float* __restrict__ knn_dist)
{
    extern __shared__ __align__(16) char smem[];
    int y = blockIdx.y, b = blockIdx.z;
    if (y == 5) {
        if (blockIdx.x < 64) geo_body(coords, knn_idx, knn_dist, blockIdx.x, b);
        return;
    }
    if (y == 0)
        conv_dev<128, 128, EPI_LEAKY02, 8>(smem, blockIdx.x * 128, 0, b,
            wh + WOFF_W1, b1, fT, x1, nullptr, nullptr, nullptr, nullptr, nullptr);
    else
        conv_dev<512, 128, EPI_TRANS_STATS, 32>(smem, blockIdx.x * 128,
            (y - 1) * 128, b, wh + WOFF_SC, sc_b, fT, scp,
            nullptr, nullptr, nullptr, scs, scq);
}

// ---------------- normalize p2 -> x3 with inline fin2 ----------------------
__global__ __launch_bounds__(256) void normalize_h_kernel(
    const __half* __restrict__ p, __half* __restrict__ x,
    const float* __restrict__ sums, const float* __restrict__ sqs,
    const float* __restrict__ gw, const float* __restrict__ gb)
{
    size_t i = ((size_t)blockIdx.x * blockDim.x + threadIdx.x) * 4;
    int c = (int)(i % 256);
    int b = (int)(i / ((size_t)Nc * 256));
    const float Minv = 1.f / (16.f * Nc);
    int g = c >> 4;
    float mean = sums[b * 16 + g] * Minv;
    float var = fmaxf(sqs[b * 16 + g] * Minv - mean * mean, 0.f);
    float rstd = rsqrtf(var + 1e-6f);
    __half2 v0 = *(const __half2*)(p + i);
    __half2 v1 = *(const __half2*)(p + i + 2);
    float vv[4] = {__half2float(v0.x), __half2float(v0.y),
                   __half2float(v1.x), __half2float(v1.y)};
    float rr[4];
#pragma unroll
    for (int e = 0; e < 4; ++e) {
        float a = rstd * gw[c + e];
        float cc = gb[c + e] - mean * a;
        rr[e] = fmaxf(fmaf(vv[e], a, cc), 0.f);
    }
    *(__half2*)(x + i) = __floats2half2_rn(rr[0], rr[1]);
    *(__half2*)(x + i + 2) = __floats2half2_rn(rr[2], rr[3]);
}

// ---------------- fused LSE (float4 geo; AFF derives pool1 affine inline) ---
static constexpr int PTS = 8;
template <bool AFF>
__global__ __launch_bounds__(128) void lse_apply_kernel(
    const float* __restrict__ coords, const int* __restrict__ knn_idx,
    const float* __restrict__ knn_dist, const float* __restrict__ w,
    const float* __restrict__ aArr, const float* __restrict__ cArr,
    const __half* __restrict__ xsrc, __half* __restrict__ mout,
    const float* __restrict__ sums, const float* __restrict__ sqs,
    const float* __restrict__ pgw, const float* __restrict__ pgb)
{
    __shared__ int sh_idx[PTS * 16];
    __shared__ float4 sh_g[PTS * 16];   // nbr.xyz, dist
    __shared__ float sh_ctr[PTS][3];
    __shared__ float2 spart[PTS][64];

    const int b = blockIdx.y;
    const int n0 = blockIdx.x * PTS;
    const int tid = threadIdx.x;
    const float* cb = coords + (size_t)b * Nc * 3;

    float ddv;
    if (tid < PTS * 16) {
        size_t base = ((size_t)b * Nc + n0) * 16 + tid;
        sh_idx[tid] = knn_idx[base];
        ddv = knn_dist[base];
    }
    if (tid < PTS * 3) sh_ctr[tid / 3][tid % 3] = cb[n0 * 3 + tid];
    __syncthreads();
    if (tid < PTS * 16) {
        int j = sh_idx[tid];
        sh_g[tid] = make_float4(cb[j * 3 + 0], cb[j * 3 + 1], cb[j * 3 + 2], ddv);
    }
    float w0 = w[tid * 10 + 0], w1 = w[tid * 10 + 1], w2 = w[tid * 10 + 2];
    float w3 = w[tid * 10 + 3], w4 = w[tid * 10 + 4], w5 = w[tid * 10 + 5];
    float w6 = w[tid * 10 + 6], w7 = w[tid * 10 + 7], w8 = w[tid * 10 + 8];
    float wd = w[tid * 10 + 9];
    const float wcx = w0 + w6, wcy = w1 + w7, wcz = w2 + w8;
    const float wnx = w3 - w6, wny = w4 - w7, wnz = w5 - w8;
    const float a = aArr[b * 128 + tid];
    const float cc = cArr[b * 128 + tid];

    const int cp = tid & 63, h = tid >> 6;
    float an0 = 0.f, an1 = 0.f, cn0 = 0.f, cn1 = 0.f;
    if (AFF) {
        const float Minv = 1.f / (8.f * Nc);
        int ch0 = 2 * cp;
        int g = ch0 >> 3;
        float mean = sums[b * 16 + g] * Minv;
        float var = fmaxf(sqs[b * 16 + g] * Minv - mean * mean, 0.f);
        float rstd = rsqrtf(var + 1e-6f);
        an0 = rstd * pgw[ch0];
        cn0 = pgb[ch0] - mean * an0;
        an1 = rstd * pgw[ch0 + 1];
        cn1 = pgb[ch0 + 1] - mean * an1;
    }
    const __half* xb = xsrc + (size_t)b * Nc * 128;
    __syncthreads();

    float2 accn[PTS];
#pragma unroll
    for (int pi = 0; pi < PTS; pi++) {
        float cx = sh_ctr[pi][0], cy = sh_ctr[pi][1], cz = sh_ctr[pi][2];
        float dotc = wcx * cx + wcy * cy + wcz * cz;
        float accg = 0.f;
#pragma unroll
        for (int k = 0; k < 16; k++) {
            float4 gv = sh_g[pi * 16 + k];
            float dot = dotc + wnx * gv.x + wny * gv.y + wnz * gv.z + wd * gv.w;
            accg += fmaxf(fmaf(dot, a, cc), 0.f);
        }
        mout[((size_t)b * Nc + n0 + pi) * 256 + tid] = __float2half(accg * 0.0625f);

        float2 acc = make_float2(0.f, 0.f);
#pragma unroll
        for (int k = 0; k < 8; k++) {
            int s = pi * 16 + h * 8 + k;
            int j = sh_idx[s];
            float2 f = __half22float2(*(const __half2*)&xb[(size_t)j * 128 + 2 * cp]);
            if (AFF) {
                f.x = fmaxf(fmaf(f.x, an0, cn0), 0.f);
                f.y = fmaxf(fmaf(f.y, an1, cn1), 0.f);
            }
            acc.x += f.x; acc.y += f.y;
        }
        if (h == 1) spart[pi][cp] = acc;
        accn[pi] = acc;
    }
    __syncthreads();
    if (h == 0) {
#pragma unroll
        for (int pi = 0; pi < PTS; pi++) {
            float2 o = spart[pi][cp];
            o.x = (o.x + accn[pi].x) * 0.0625f;
            o.y = (o.y + accn[pi].y) * 0.0625f;
            *(__half2*)&mout[((size_t)b * Nc + n0 + pi) * 256 + 128 + 2 * cp] =
                __floats2half2_rn(o.x, o.y);
        }
    }
}

// ---------------- host ----------------
#define SYM(ty, p, s) do { void* _t; cudaGetSymbolAddress(&_t, s); p = (ty)_t; } while (0)

extern "C" void kernel_launch(void* const* d_in, const int* in_sizes, int n_in,
                              void* d_out, int out_size)
{
    (void)in_sizes; (void)n_in; (void)out_size;
    const float* coords   = (const float*)d_in[0];
    const float* features = (const float*)d_in[1];
    const float* knn_dist = (const float*)d_in[2];
    const int*   knn_idx  = (const int*)d_in[3];
    const float* w1       = (const float*)d_in[4];
    const float* b1       = (const float*)d_in[5];
    const float* lse1_w   = (const float*)d_in[6];
    const float* lse1_b   = (const float*)d_in[7];
    const float* lse1_gw  = (const float*)d_in[8];
    const float* lse1_gb  = (const float*)d_in[9];
    const float* pool1_w  = (const float*)d_in[10];
    const float* pool1_b  = (const float*)d_in[11];
    const float* pool1_gw = (const float*)d_in[12];
    const float* pool1_gb = (const float*)d_in[13];
    const float* lse2_w   = (const float*)d_in[14];
    const float* lse2_b   = (const float*)d_in[15];
    const float* lse2_gw  = (const float*)d_in[16];
    const float* lse2_gb  = (const float*)d_in[17];
    const float* pool2_w  = (const float*)d_in[18];
    const float* pool2_b  = (const float*)d_in[19];
    const float* pool2_gw = (const float*)d_in[20];
    const float* pool2_gb = (const float*)d_in[21];
    const float* mlp2_w   = (const float*)d_in[22];
    const float* mlp2_b   = (const float*)d_in[23];
    const float* sc_w     = (const float*)d_in[24];
    const float* sc_b     = (const float*)d_in[25];
    const float* sc_gw    = (const float*)d_in[26];
    const float* sc_gb    = (const float*)d_in[27];
    float* out = (float*)d_out;

    __half *fT, *wh, *x1, *m1, *p1, *m2, *p2, *x3, *scp;
    float *l1a, *l1c, *l2a, *l2c;
    float *p1s, *p1q, *p2s, *p2q, *scs, *scq;
    SYM(__half*, fT, g_fT); SYM(__half*, wh, g_wh);
    SYM(__half*, x1, g_x1); SYM(__half*, m1, g_m1); SYM(__half*, p1, g_p1);
    SYM(__half*, m2, g_m2); SYM(__half*, p2, g_p2); SYM(__half*, x3, g_x3);
    SYM(__half*, scp, g_scp);
    SYM(float*, l1a, g_lse1a); SYM(float*, l1c, g_lse1c);
    SYM(float*, l2a, g_lse2a); SYM(float*, l2c, g_lse2c);
    SYM(float*, p1s, g_p1s); SYM(float*, p1q, g_p1q);
    SYM(float*, p2s, g_p2s); SYM(float*, p2q, g_p2q);
    SYM(float*, scs, g_scs); SYM(float*, scq, g_scq);

    cudaFuncSetAttribute(fused_a_kernel,
                         cudaFuncAttributeMaxDynamicSharedMemorySize, CONV_SMEM);
    cudaFuncSetAttribute(mma_conv_k<128, 256, EPI_STATS, 8>,
                         cudaFuncAttributeMaxDynamicSharedMemorySize, CONV_SMEM);
    cudaFuncSetAttribute(mma_conv_k<256, 256, EPI_STATS, 16>,
                         cudaFuncAttributeMaxDynamicSharedMemorySize, CONV_SMEM);
    cudaFuncSetAttribute(mma_conv_k<512, 256, EPI_FINAL, 32>,
                         cudaFuncAttributeMaxDynamicSharedMemorySize, CONV_SMEM);

    // K1: zero stats + weight convert + feature transpose
    prep_transpose_kernel<<<4096 + 256, 256>>>(w1, pool1_w, pool2_w, sc_w,
                                               mlp2_w, features, fT);
    // K2: mlp1 (y=0) + shortcut conv (y=1..4) + geo moments (y=5)
    fused_a_kernel<<<dim3(Nc / 128, 6, Bc), 256, CONV_SMEM>>>(
        wh, b1, sc_b, fT, x1, scp, scs, scq, coords, knn_idx, knn_dist);
    // K3: closed-form GN for both LSE layers (fp32)
    lse_finalize_kernel<<<dim3(Bc, 2), 128>>>(lse1_w, lse1_b, lse1_gw, lse1_gb,
                                              lse2_w, lse2_b, lse2_gw, lse2_gb,
                                              l1a, l1c, l2a, l2c);
    // K4: lse1
    lse_apply_kernel<false><<<dim3(Nc / PTS, Bc), 128>>>(
        coords, knn_idx, knn_dist, lse1_w, l1a, l1c, x1, m1,
        nullptr, nullptr, nullptr, nullptr);
    // K5: pool1 conv + stats
    mma_conv_k<128, 256, EPI_STATS, 8>
        <<<dim3(Nc / 128, 1, Bc), 256, CONV_SMEM>>>(wh + WOFF_P1, pool1_b, m1, p1,
                                                    nullptr, nullptr, nullptr,
                                                    p1s, p1q);
    // K6: lse2 (inline pool1 GN finalize)
    lse_apply_kernel<true><<<dim3(Nc / PTS, Bc), 128>>>(
        coords, knn_idx, knn_dist, lse2_w, l2a, l2c, p1, m2,
        p1s, p1q, pool1_gw, pool1_gb);
    // K7: pool2 conv + stats
    mma_conv_k<256, 256, EPI_STATS, 16>
        <<<dim3(Nc / 128, 2, Bc), 256, CONV_SMEM>>>(wh + WOFF_P2, pool2_b, m2, p2,
                                                    nullptr, nullptr, nullptr,
                                                    p2s, p2q);
    // K8: normalize (inline pool2 GN finalize)
    normalize_h_kernel<<<(Bc * Nc * 256) / 1024, 256>>>(p2, x3, p2s, p2q,
                                                        pool2_gw, pool2_gb);
    // K9: final conv + inline shortcut GN + leaky(0.01) -> out [b][o][n] fp32
    mma_conv_k<512, 256, EPI_FINAL, 32>
        <<<dim3(Nc / 128, 4, Bc), 256, CONV_SMEM>>>(wh + WOFF_M2, mlp2_b, x3, out,
                                                    scp, sc_gw, sc_gb, scs, scq);
}

// round 13
// speedup vs baseline: 1.1471x; 1.0196x over previous
#include <cuda_runtime.h>
#include <cuda_fp16.h>
#include <stdint.h>
#include <math.h>

static constexpr int Bc = 2;
static constexpr int Nc = 16384;
static constexpr int Kc = 16;

// ---------------- scratch ----------------
__device__ __half g_fT[(size_t)Bc * Nc * 128];   // features transposed [b][n][c]
__device__ __half g_wh[311296];                  // all conv weights as fp16
__device__ __half g_x1[(size_t)Bc * Nc * 128];   // mlp1 out  [b][n][c]
__device__ __half g_m1[(size_t)Bc * Nc * 256];   // lse1 pooled mean
__device__ __half g_p1[(size_t)Bc * Nc * 128];   // pool1 pre-GN
__device__ __half g_m2[(size_t)Bc * Nc * 256];   // lse2 pooled mean
__device__ __half g_p2[(size_t)Bc * Nc * 256];   // pool2 pre-GN
__device__ __half g_x3[(size_t)Bc * Nc * 256];   // pool2 out
__device__ __half g_scp[(size_t)Bc * Nc * 512];  // shortcut pre-GN, [b][o][n] fp16

__device__ double g_geoS[Bc * 10];
__device__ double g_geoG[Bc * 55];
__device__ float4 g_lw1[Bc * 128 * 2];   // lse1 prefolded: {a*wc.xyz, cc},{a*wn.xyz, a*wd}
__device__ float4 g_lw2[Bc * 128 * 2];   // lse2 prefolded
__device__ float g_p1s[Bc * 16], g_p1q[Bc * 16];
__device__ float g_p2s[Bc * 16], g_p2q[Bc * 16];
__device__ float g_scs[Bc * 16], g_scq[Bc * 16];

// weight blob offsets (in halves)
static constexpr int WOFF_W1 = 0;
static constexpr int WOFF_P1 = 16384;
static constexpr int WOFF_P2 = 49152;
static constexpr int WOFF_SC = 114688;
static constexpr int WOFF_M2 = 180224;
static constexpr int WTOT = 311296;

// ---------------- helpers ----------------
__device__ __forceinline__ uint32_t smem_u32(const void* p) {
    uint32_t a;
    asm("{ .reg .u64 t; cvta.to.shared.u64 t, %1; cvt.u32.u64 %0, t; }" : "=r"(a) : "l"(p));
    return a;
}
__device__ __forceinline__ void cpa16(uint32_t dst, const void* src) {
    asm volatile("cp.async.cg.shared.global [%0], [%1], 16;" :: "r"(dst), "l"(src));
}
#define CP_COMMIT() asm volatile("cp.async.commit_group;" ::: "memory")
#define CP_WAIT1() asm volatile("cp.async.wait_group 1;" ::: "memory")
#define CP_WAIT0() asm volatile("cp.async.wait_group 0;" ::: "memory")

#define MMA_F16(d, a, b) \
    asm volatile("mma.sync.aligned.m16n8k16.row.col.f32.f16.f16.f32 " \
        "{%0,%1,%2,%3}, {%4,%5,%6,%7}, {%8,%9}, {%0,%1,%2,%3};" \
        : "+f"((d)[0]), "+f"((d)[1]), "+f"((d)[2]), "+f"((d)[3]) \
        : "r"((a)[0]), "r"((a)[1]), "r"((a)[2]), "r"((a)[3]), \
          "r"((b)[0]), "r"((b)[1]))

#define LDSM4(r, addr) \
    asm volatile("ldmatrix.sync.aligned.m8n8.x4.shared.b16 {%0,%1,%2,%3}, [%4];" \
        : "=r"((r)[0]), "=r"((r)[1]), "=r"((r)[2]), "=r"((r)[3]) : "r"(addr))

// swizzled offset within a row-major 128B-row tile: row r, 16B-chunk c (0..7)
__device__ __forceinline__ uint32_t swoff(int r, int c) {
    return (uint32_t)(r * 128 + ((c ^ (r & 7)) << 4));
}

enum { EPI_LEAKY02 = 0, EPI_STATS = 1, EPI_TRANS_STATS = 2, EPI_FINAL = 3 };
static constexpr int CONV_SMEM = 3 * 32768 + 256;
static constexpr int OSH_STRIDE = 136;

// ---------------- K1: zero stats + convert weights + transpose -------------
__global__ __launch_bounds__(256) void prep_transpose_kernel(
    const float* __restrict__ w1, const float* __restrict__ pw1,
    const float* __restrict__ pw2, const float* __restrict__ scw,
    const float* __restrict__ mw,
    const float* __restrict__ features, __half* __restrict__ fT)
{
    __shared__ float t[32][33];
    int bid = blockIdx.x;
    if (bid < 4096) {
        int b = bid >> 11;
        int rem = bid & 2047;
        int cB = (rem >> 9) * 32, nB = (rem & 511) * 32;
        int tx = threadIdx.x & 31, ty = threadIdx.x >> 5;
#pragma unroll
        for (int i = 0; i < 4; ++i)
            t[ty + 8 * i][tx] =
                features[((size_t)b * 128 + cB + ty + 8 * i) * Nc + nB + tx];
        __syncthreads();
#pragma unroll
        for (int i = 0; i < 4; ++i)
            fT[((size_t)b * Nc + nB + ty + 8 * i) * 128 + cB + tx] =
                __float2half(t[tx][ty + 8 * i]);
    } else {
        int cb = bid - 4096;  // 0..255
        if (cb == 0) {
            int tt = threadIdx.x;
            if (tt < Bc * 10) g_geoS[tt] = 0.0;
            if (tt < Bc * 55) g_geoG[tt] = 0.0;
            if (tt < Bc * 16) {
                g_p1s[tt] = 0.f; g_p1q[tt] = 0.f;
                g_p2s[tt] = 0.f; g_p2q[tt] = 0.f;
                g_scs[tt] = 0.f; g_scq[tt] = 0.f;
            }
        }
        for (int i = cb * 256 + threadIdx.x; i < WTOT; i += 256 * 256) {
            float v;
            if (i < WOFF_P1) v = w1[i];
            else if (i < WOFF_P2) v = pw1[i - WOFF_P1];
            else if (i < WOFF_SC) v = pw2[i - WOFF_P2];
            else if (i < WOFF_M2) v = scw[i - WOFF_SC];
            else v = mw[i - WOFF_M2];
            g_wh[i] = __float2half(v);
        }
    }
}

// ---------------- geo moments (device body) ----------------
__device__ void geo_body(const float* __restrict__ coords,
                         const int* __restrict__ knn_idx,
                         const float* __restrict__ knn_dist, int bx, int b)
{
    const float* cb = coords + (size_t)b * Nc * 3;
    float S[10];
    float G[55];
#pragma unroll
    for (int c = 0; c < 10; c++) S[c] = 0.f;
#pragma unroll
    for (int p = 0; p < 55; p++) G[p] = 0.f;

    for (int it = bx * 256 + threadIdx.x; it < Nc * Kc; it += 64 * 256) {
        int n = it >> 4;
        size_t base = ((size_t)b * Nc + n) * Kc + (it & 15);
        float cx = cb[n * 3 + 0], cy = cb[n * 3 + 1], cz = cb[n * 3 + 2];
        int j = knn_idx[base];
        float nx = cb[j * 3 + 0], ny = cb[j * 3 + 1], nz = cb[j * 3 + 2];
        float dd = knn_dist[base];
        float g[10] = {cx, cy, cz, nx, ny, nz, cx - nx, cy - ny, cz - nz, dd};
        int p = 0;
#pragma unroll
        for (int c = 0; c < 10; c++) {
            S[c] += g[c];
#pragma unroll
            for (int d = c; d < 10; d++) G[p++] += g[c] * g[d];
        }
    }
#pragma unroll
    for (int c = 0; c < 10; c++)
        for (int off = 16; off; off >>= 1) S[c] += __shfl_xor_sync(~0u, S[c], off);
#pragma unroll
    for (int p = 0; p < 55; p++)
        for (int off = 16; off; off >>= 1) G[p] += __shfl_xor_sync(~0u, G[p], off);
    if ((threadIdx.x & 31) == 0) {
        for (int c = 0; c < 10; c++) atomicAdd(&g_geoS[b * 10 + c], (double)S[c]);
        for (int p = 0; p < 55; p++) atomicAdd(&g_geoG[b * 55 + p], (double)G[p]);
    }
}

// ---------------- closed-form GN stats (fp32) -> prefolded lse weights -----
__global__ void lse_finalize_kernel(
    const float* __restrict__ w1p, const float* __restrict__ b1p,
    const float* __restrict__ gw1, const float* __restrict__ gb1,
    const float* __restrict__ w2p, const float* __restrict__ b2p,
    const float* __restrict__ gw2, const float* __restrict__ gb2)
{
    int b = blockIdx.x;
    int layer = blockIdx.y;
    const float* w = layer ? w2p : w1p;
    const float* bias = layer ? b2p : b1p;
    const float* gw = layer ? gw2 : gw1;
    const float* gb = layer ? gb2 : gb1;
    float4* lw = layer ? g_lw2 : g_lw1;

    __shared__ float sS[10], sG[55];
    int o = threadIdx.x;  // 128
    if (o < 10) sS[o] = (float)g_geoS[b * 10 + o];
    if (o < 55) sG[o] = (float)g_geoG[b * 55 + o];
    __syncthreads();

    float wr[10];
#pragma unroll
    for (int c = 0; c < 10; c++) wr[c] = w[o * 10 + c];
    float t1 = 0.f;
#pragma unroll
    for (int c = 0; c < 10; c++) t1 += wr[c] * sS[c];
    float t2 = 0.f;
    int p = 0;
#pragma unroll
    for (int c = 0; c < 10; c++)
#pragma unroll
        for (int d = c; d < 10; d++) {
            float ww = wr[c] * wr[d];
            t2 += (c == d ? ww : 2.f * ww) * sG[p];
            p++;
        }
    const float NK = (float)Nc * (float)Kc;
    float bo = bias[o];
    float sum = t1 + bo * NK;
    float sq = t2 + 2.f * bo * t1 + bo * bo * NK;
#pragma unroll
    for (int off = 1; off < 8; off <<= 1) {
        sum += __shfl_xor_sync(~0u, sum, off);
        sq += __shfl_xor_sync(~0u, sq, off);
    }
    float M = 8.f * NK;
    float mean = sum / M;
    float var = fmaxf(sq / M - mean * mean, 0.f);
    float rstd = rsqrtf(var + 1e-6f);
    float a = rstd * gw[o];
    float cc = gb[o] + (bo - mean) * a;
    // prefold a into combined geometry weights
    lw[(b * 128 + o) * 2 + 0] =
        make_float4(a * (wr[0] + wr[6]), a * (wr[1] + wr[7]), a * (wr[2] + wr[8]), cc);
    lw[(b * 128 + o) * 2 + 1] =
        make_float4(a * (wr[3] - wr[6]), a * (wr[4] - wr[7]), a * (wr[5] - wr[8]), a * wr[9]);
}

// ---------------- conv device body: 128n x 128o tile, 64-col K chunks ------
template <int O, int C, int EPI, int GSIZE>
__device__ __forceinline__ void conv_dev(
    char* smem, int n0, int o0, int b,
    const __half* __restrict__ Wh, const float* __restrict__ bias,
    const __half* __restrict__ in, void* __restrict__ outv,
    const __half* __restrict__ scpre,
    const float* __restrict__ scgw, const float* __restrict__ scgb,
    float* gsum, float* gsq)
{
    const uint32_t sb = smem_u32(smem);
    float* ssh = (float*)(smem + 98304);
    float* sqh = ssh + 16;
    float* osf = (float*)smem;
    __half* osh = (__half*)smem;

    const int tid = threadIdx.x;
    const int w = tid >> 5, lane = tid & 31;
    const int wr = w & 1, wc = w >> 1;
    const int t = lane & 3, g = lane >> 2;

    const __half* xbase = in + ((size_t)b * Nc + n0) * C;
    const __half* wbase = Wh + (size_t)o0 * C;

    uint32_t sOff[4];
    const __half* gxp[4];
    const __half* gwp[4];
#pragma unroll
    for (int i = 0; i < 4; ++i) {
        int id = tid + 256 * i;
        int r = id >> 3, c = id & 7;
        sOff[i] = swoff(r, c);
        gxp[i] = xbase + (size_t)r * C + c * 8;
        gwp[i] = wbase + (size_t)r * C + c * 8;
    }

    const int quad = lane >> 3, lr = lane & 7;
    const int raA = (quad & 1) * 8 + lr, caA = quad >> 1;
    const int raB = (quad >> 1) * 8 + lr, caB = quad & 1;
    uint32_t rbA[4], rxA[4];
#pragma unroll
    for (int mi = 0; mi < 4; ++mi) {
        int row = wr * 64 + mi * 16 + raA;
        rbA[mi] = (uint32_t)(row * 128);
        rxA[mi] = (uint32_t)(row & 7);
    }
    uint32_t rbB[2], rxB[2];
#pragma unroll
    for (int oi = 0; oi < 2; ++oi) {
        int row = wc * 32 + oi * 16 + raB;
        rbB[oi] = 16384u + (uint32_t)(row * 128);
        rxB[oi] = (uint32_t)(row & 7);
    }

    float d[4][4][4];
#pragma unroll
    for (int mi = 0; mi < 4; ++mi)
#pragma unroll
        for (int ni = 0; ni < 4; ++ni)
#pragma unroll
            for (int e = 0; e < 4; ++e) d[mi][ni][e] = 0.f;

    constexpr int NCH = C / 64;
    auto stage = [&](int j) {
        uint32_t base = sb + (uint32_t)(j % 3) * 32768u;
        int cc = j * 64;
#pragma unroll
        for (int i = 0; i < 4; ++i) {
            cpa16(base + sOff[i], gxp[i] + cc);
            cpa16(base + 16384 + sOff[i], gwp[i] + cc);
        }
        CP_COMMIT();
    };
    stage(0);
    if (NCH > 1) stage(1);

    for (int j = 0; j < NCH; ++j) {
        if (j + 1 < NCH) CP_WAIT1(); else CP_WAIT0();
        __syncthreads();
        if (j + 2 < NCH) stage(j + 2);
        const uint32_t base = sb + (uint32_t)(j % 3) * 32768u;
#pragma unroll
        for (int kt = 0; kt < 4; ++kt) {
            uint32_t a[4][4], bb[2][4];
#pragma unroll
            for (int mi = 0; mi < 4; ++mi) {
                uint32_t cA = (uint32_t)(kt * 2 + caA) ^ rxA[mi];
                LDSM4(a[mi], base + rbA[mi] + (cA << 4));
            }
#pragma unroll
            for (int oi = 0; oi < 2; ++oi) {
                uint32_t cB = (uint32_t)(kt * 2 + caB) ^ rxB[oi];
                LDSM4(bb[oi], base + rbB[oi] + (cB << 4));
            }
#pragma unroll
            for (int mi = 0; mi < 4; ++mi)
#pragma unroll
                for (int ni = 0; ni < 4; ++ni) {
                    uint32_t bf[2] = {bb[ni >> 1][(ni & 1) * 2],
                                      bb[ni >> 1][(ni & 1) * 2 + 1]};
                    MMA_F16(d[mi][ni], a[mi], bf);
                }
        }
    }

    // ================= epilogues =================
    if constexpr (EPI == EPI_LEAKY02 || EPI == EPI_STATS) {
        __half* out = (__half*)outv;
        __syncthreads();
        if constexpr (EPI == EPI_STATS) {
            if (tid < 16) { ssh[tid] = 0.f; sqh[tid] = 0.f; }
            __syncthreads();
        }
        float js[4] = {0.f, 0.f, 0.f, 0.f}, jq[4] = {0.f, 0.f, 0.f, 0.f};
#pragma unroll
        for (int mi = 0; mi < 4; ++mi) {
            int p = wr * 64 + mi * 16 + g;
#pragma unroll
            for (int ni = 0; ni < 4; ++ni) {
                int ch = wc * 32 + ni * 8 + 2 * t;
                float b0 = bias[o0 + ch], b1 = bias[o0 + ch + 1];
                float v00 = d[mi][ni][0] + b0, v01 = d[mi][ni][1] + b1;
                float v10 = d[mi][ni][2] + b0, v11 = d[mi][ni][3] + b1;
                if constexpr (EPI == EPI_LEAKY02) {
                    v00 = v00 > 0.f ? v00 : 0.2f * v00;
                    v01 = v01 > 0.f ? v01 : 0.2f * v01;
                    v10 = v10 > 0.f ? v10 : 0.2f * v10;
                    v11 = v11 > 0.f ? v11 : 0.2f * v11;
                } else {
                    js[ni] += v00 + v01 + v10 + v11;
                    jq[ni] += v00 * v00 + v01 * v01 + v10 * v10 + v11 * v11;
                }
                *(__half2*)&osh[p * OSH_STRIDE + ch] = __floats2half2_rn(v00, v01);
                *(__half2*)&osh[(p + 8) * OSH_STRIDE + ch] = __floats2half2_rn(v10, v11);
            }
        }
        if constexpr (EPI == EPI_STATS) {
#pragma unroll
            for (int ni = 0; ni < 4; ++ni) {
                int gl = (wc * 32 + ni * 8) / GSIZE;
                atomicAdd(&ssh[gl], js[ni]);
                atomicAdd(&sqh[gl], jq[ni]);
            }
        }
        __syncthreads();
#pragma unroll
        for (int i = 0; i < 8; ++i) {
            int id = tid + 256 * i;
            int row = id >> 4, c16 = id & 15;
            uint4 v = *(uint4*)&osh[row * OSH_STRIDE + c16 * 8];
            *(uint4*)&out[((size_t)b * Nc + n0 + row) * O + o0 + c16 * 8] = v;
        }
        if constexpr (EPI == EPI_STATS) {
            constexpr int NG = 128 / GSIZE;
            if (tid < NG) {
                atomicAdd(&gsum[b * 16 + o0 / GSIZE + tid], ssh[tid]);
                atomicAdd(&gsq[b * 16 + o0 / GSIZE + tid], sqh[tid]);
            }
        }
    } else {
        __syncthreads();
        if (tid < 16) { ssh[tid] = 0.f; sqh[tid] = 0.f; }
        __syncthreads();
#pragma unroll
        for (int p = 0; p < 2; ++p) {
            if ((wc >> 1) == p) {
                float js[4] = {0.f, 0.f, 0.f, 0.f}, jq[4] = {0.f, 0.f, 0.f, 0.f};
#pragma unroll
                for (int mi = 0; mi < 4; ++mi) {
                    int nr = wr * 64 + mi * 16 + g;
#pragma unroll
                    for (int ni = 0; ni < 4; ++ni) {
                        int oc = (wc & 1) * 32 + ni * 8 + 2 * t;
                        float b0 = 0.f, b1 = 0.f;
                        if constexpr (EPI == EPI_TRANS_STATS) {
                            b0 = bias[o0 + p * 64 + oc];
                            b1 = bias[o0 + p * 64 + oc + 1];
                        }
                        float v00 = d[mi][ni][0] + b0, v01 = d[mi][ni][1] + b1;
                        float v10 = d[mi][ni][2] + b0, v11 = d[mi][ni][3] + b1;
                        if constexpr (EPI == EPI_TRANS_STATS) {
                            js[ni] += v00 + v01 + v10 + v11;
                            jq[ni] += v00 * v00 + v01 * v01 + v10 * v10 + v11 * v11;
                        }
                        osf[oc * 132 + nr] = v00;
                        osf[(oc + 1) * 132 + nr] = v01;
                        osf[oc * 132 + nr + 8] = v10;
                        osf[(oc + 1) * 132 + nr + 8] = v11;
                    }
                }
                if constexpr (EPI == EPI_TRANS_STATS) {
#pragma unroll
                    for (int ni = 0; ni < 4; ++ni) {
                        int gl = (p * 64 + (wc & 1) * 32 + ni * 8) / GSIZE;
                        atomicAdd(&ssh[gl], js[ni]);
                        atomicAdd(&sqh[gl], jq[ni]);
                    }
                }
            }
            __syncthreads();
#pragma unroll
            for (int rr = 0; rr < 8; ++rr) {
                int r = w + rr * 8;
                int og = o0 + p * 64 + r;
                float4 v = *(float4*)&osf[r * 132 + lane * 4];
                if constexpr (EPI == EPI_FINAL) {
                    float* op = (float*)outv + ((size_t)b * O + og) * Nc + n0;
                    float bi = bias[og];
                    const float Minv = 1.f / (GSIZE * (float)Nc);
                    int gg = og / GSIZE;
                    float mean = gsum[b * 16 + gg] * Minv;
                    float var = fmaxf(gsq[b * 16 + gg] * Minv - mean * mean, 0.f);
                    float rstd = rsqrtf(var + 1e-6f);
                    float av = rstd * scgw[og];
                    float cv = scgb[og] - mean * av;
                    uint2 sraw = *(const uint2*)(scpre +
                        ((size_t)b * O + og) * Nc + n0 + lane * 4);
                    float2 s0 = __half22float2(*(__half2*)&sraw.x);
                    float2 s1 = __half22float2(*(__half2*)&sraw.y);
                    float ss[4] = {s0.x, s0.y, s1.x, s1.y};
                    float4 rrv;
#pragma unroll
                    for (int e = 0; e < 4; ++e) {
                        float x = (&v.x)[e] + bi + fmaf(ss[e], av, cv);
                        (&rrv.x)[e] = x > 0.f ? x : 0.01f * x;
                    }
                    *(float4*)(op + lane * 4) = rrv;
                } else {
                    __half* op = (__half*)outv + ((size_t)b * O + og) * Nc + n0;
                    uint2 st;
                    *(__half2*)&st.x = __floats2half2_rn(v.x, v.y);
                    *(__half2*)&st.y = __floats2half2_rn(v.z, v.w);
                    *(uint2*)(op + lane * 4) = st;
                }
            }
            __syncthreads();
        }
        if constexpr (EPI == EPI_TRANS_STATS) {
            constexpr int NG = 128 / GSIZE;
            if (tid < NG) {
                atomicAdd(&gsum[b * 16 + o0 / GSIZE + tid], ssh[tid]);
                atomicAdd(&gsq[b * 16 + o0 / GSIZE + tid], sqh[tid]);
            }
        }
    }
}

// ---------------- standalone conv kernels ----------------------------------
template <int O, int C, int EPI, int GSIZE>
__global__ __launch_bounds__(256, 2) void mma_conv_k(
    const __half* __restrict__ Wh, const float* __restrict__ bias,
    const __half* __restrict__ in, void* __restrict__ outv,
    const __half* __restrict__ scpre,
    const float* __restrict__ scgw, const float* __restrict__ scgb,
    float* gsum, float* gsq)
{
    extern __shared__ __align__(16) char smem[];
    conv_dev<O, C, EPI, GSIZE>(smem, blockIdx.x * 128, blockIdx.y * 128,
                               blockIdx.z, Wh, bias, in, outv,
                               scpre, scgw, scgb, gsum, gsq);
}

// ---------------- K2: mlp1 + shortcut conv + geo moments -------------------
__global__ __launch_bounds__(256, 2) void fused_a_kernel(
    const __half* __restrict__ wh, const float* __restrict__ b1,
    const float* __restrict__ sc_b, const __half* __restrict__ fT,
    __half* __restrict__ x1, __half* __restrict__ scp,
    float* scs, float* scq,
    const float* __restrict__ coords, const int* __restrict__ knn_idx,
    const float* __restrict__ knn_dist)
{
    extern __shared__ __align__(16) char smem[];
    int y = blockIdx.y, b = blockIdx.z;
    if (y == 5) {
        if (blockIdx.x < 64) geo_body(coords, knn_idx, knn_dist, blockIdx.x, b);
        return;
    }
    if (y == 0)
        conv_dev<128, 128, EPI_LEAKY02, 8>(smem, blockIdx.x * 128, 0, b,
            wh + WOFF_W1, b1, fT, x1, nullptr, nullptr, nullptr, nullptr, nullptr);
    else
        conv_dev<512, 128, EPI_TRANS_STATS, 32>(smem, blockIdx.x * 128,
            (y - 1) * 128, b, wh + WOFF_SC, sc_b, fT, scp,
            nullptr, nullptr, nullptr, scs, scq);
}

// ---------------- normalize p2 -> x3 with inline fin2 ----------------------
__global__ __launch_bounds__(256) void normalize_h_kernel(
    const __half* __restrict__ p, __half* __restrict__ x,
    const float* __restrict__ sums, const float* __restrict__ sqs,
    const float* __restrict__ gw, const float* __restrict__ gb)
{
    size_t i = ((size_t)blockIdx.x * blockDim.x + threadIdx.x) * 4;
    int c = (int)(i % 256);
    int b = (int)(i / ((size_t)Nc * 256));
    const float Minv = 1.f / (16.f * Nc);
    int g = c >> 4;
    float mean = sums[b * 16 + g] * Minv;
    float var = fmaxf(sqs[b * 16 + g] * Minv - mean * mean, 0.f);
    float rstd = rsqrtf(var + 1e-6f);
    __half2 v0 = *(const __half2*)(p + i);
    __half2 v1 = *(const __half2*)(p + i + 2);
    float vv[4] = {__half2float(v0.x), __half2float(v0.y),
                   __half2float(v1.x), __half2float(v1.y)};
    float rr[4];
#pragma unroll
    for (int e = 0; e < 4; ++e) {
        float a = rstd * gw[c + e];
        float cc = gb[c + e] - mean * a;
        rr[e] = fmaxf(fmaf(vv[e], a, cc), 0.f);
    }
    *(__half2*)(x + i) = __floats2half2_rn(rr[0], rr[1]);
    *(__half2*)(x + i + 2) = __floats2half2_rn(rr[2], rr[3]);
}

// ---------------- fused LSE (prefolded weights; 6-op geo inner loop) --------
static constexpr int PTS = 8;
template <bool AFF>
__global__ __launch_bounds__(128) void lse_apply_kernel(
    const float* __restrict__ coords, const int* __restrict__ knn_idx,
    const float* __restrict__ knn_dist, const float4* __restrict__ lw,
    const __half* __restrict__ xsrc, __half* __restrict__ mout,
    const float* __restrict__ sums, const float* __restrict__ sqs,
    const float* __restrict__ pgw, const float* __restrict__ pgb)
{
    __shared__ int sh_idx[PTS * 16];
    __shared__ float4 sh_g[PTS * 16];   // nbr.xyz, dist
    __shared__ float sh_ctr[PTS][3];
    __shared__ float2 spart[PTS][64];

    const int b = blockIdx.y;
    const int n0 = blockIdx.x * PTS;
    const int tid = threadIdx.x;
    const float* cb = coords + (size_t)b * Nc * 3;

    float ddv;
    if (tid < PTS * 16) {
        size_t base = ((size_t)b * Nc + n0) * 16 + tid;
        sh_idx[tid] = knn_idx[base];
        ddv = knn_dist[base];
    }
    if (tid < PTS * 3) sh_ctr[tid / 3][tid % 3] = cb[n0 * 3 + tid];
    __syncthreads();
    if (tid < PTS * 16) {
        int j = sh_idx[tid];
        sh_g[tid] = make_float4(cb[j * 3 + 0], cb[j * 3 + 1], cb[j * 3 + 2], ddv);
    }
    // prefolded weights: f0 = {a*wc.xyz, cc}, f1 = {a*wn.xyz, a*wd}
    const float4 f0 = lw[(b * 128 + tid) * 2 + 0];
    const float4 f1 = lw[(b * 128 + tid) * 2 + 1];

    const int cp = tid & 63, h = tid >> 6;
    float an0 = 0.f, an1 = 0.f, cn0 = 0.f, cn1 = 0.f;
    if (AFF) {
        const float Minv = 1.f / (8.f * Nc);
        int ch0 = 2 * cp;
        int g = ch0 >> 3;
        float mean = sums[b * 16 + g] * Minv;
        float var = fmaxf(sqs[b * 16 + g] * Minv - mean * mean, 0.f);
        float rstd = rsqrtf(var + 1e-6f);
        an0 = rstd * pgw[ch0];
        cn0 = pgb[ch0] - mean * an0;
        an1 = rstd * pgw[ch0 + 1];
        cn1 = pgb[ch0 + 1] - mean * an1;
    }
    const __half* xb = xsrc + (size_t)b * Nc * 128;
    __syncthreads();

    float2 accn[PTS];
#pragma unroll
    for (int pi = 0; pi < PTS; pi++) {
        // geo: channel tid, 4-FMA inner loop with prefolded weights
        float dotc = fmaf(f0.x, sh_ctr[pi][0],
                     fmaf(f0.y, sh_ctr[pi][1],
                     fmaf(f0.z, sh_ctr[pi][2], f0.w)));
        float accg = 0.f;
#pragma unroll
        for (int k = 0; k < 16; k++) {
            float4 gv = sh_g[pi * 16 + k];
            float dot = fmaf(f1.x, gv.x, fmaf(f1.y, gv.y,
                        fmaf(f1.z, gv.z, fmaf(f1.w, gv.w, dotc))));
            accg += fmaxf(dot, 0.f);
        }
        mout[((size_t)b * Nc + n0 + pi) * 256 + tid] = __float2half(accg * 0.0625f);

        float2 acc = make_float2(0.f, 0.f);
#pragma unroll
        for (int k = 0; k < 8; k++) {
            int s = pi * 16 + h * 8 + k;
            int j = sh_idx[s];
            float2 f = __half22float2(*(const __half2*)&xb[(size_t)j * 128 + 2 * cp]);
            if (AFF) {
                f.x = fmaxf(fmaf(f.x, an0, cn0), 0.f);
                f.y = fmaxf(fmaf(f.y, an1, cn1), 0.f);
            }
            acc.x += f.x; acc.y += f.y;
        }
        if (h == 1) spart[pi][cp] = acc;
        accn[pi] = acc;
    }
    __syncthreads();
    if (h == 0) {
#pragma unroll
        for (int pi = 0; pi < PTS; pi++) {
            float2 o = spart[pi][cp];
            o.x = (o.x + accn[pi].x) * 0.0625f;
            o.y = (o.y + accn[pi].y) * 0.0625f;
            *(__half2*)&mout[((size_t)b * Nc + n0 + pi) * 256 + 128 + 2 * cp] =
                __floats2half2_rn(o.x, o.y);
        }
    }
}

// ---------------- host ----------------
#define SYM(ty, p, s) do { void* _t; cudaGetSymbolAddress(&_t, s); p = (ty)_t; } while (0)

extern "C" void kernel_launch(void* const* d_in, const int* in_sizes, int n_in,
                              void* d_out, int out_size)
{
    (void)in_sizes; (void)n_in; (void)out_size;
    const float* coords   = (const float*)d_in[0];
    const float* features = (const float*)d_in[1];
    const float* knn_dist = (const float*)d_in[2];
    const int*   knn_idx  = (const int*)d_in[3];
    const float* w1       = (const float*)d_in[4];
    const float* b1       = (const float*)d_in[5];
    const float* lse1_w   = (const float*)d_in[6];
    const float* lse1_b   = (const float*)d_in[7];
    const float* lse1_gw  = (const float*)d_in[8];
    const float* lse1_gb  = (const float*)d_in[9];
    const float* pool1_w  = (const float*)d_in[10];
    const float* pool1_b  = (const float*)d_in[11];
    const float* pool1_gw = (const float*)d_in[12];
    const float* pool1_gb = (const float*)d_in[13];
    const float* lse2_w   = (const float*)d_in[14];
    const float* lse2_b   = (const float*)d_in[15];
    const float* lse2_gw  = (const float*)d_in[16];
    const float* lse2_gb  = (const float*)d_in[17];
    const float* pool2_w  = (const float*)d_in[18];
    const float* pool2_b  = (const float*)d_in[19];
    const float* pool2_gw = (const float*)d_in[20];
    const float* pool2_gb = (const float*)d_in[21];
    const float* mlp2_w   = (const float*)d_in[22];
    const float* mlp2_b   = (const float*)d_in[23];
    const float* sc_w     = (const float*)d_in[24];
    const float* sc_b     = (const float*)d_in[25];
    const float* sc_gw    = (const float*)d_in[26];
    const float* sc_gb    = (const float*)d_in[27];
    float* out = (float*)d_out;

    __half *fT, *wh, *x1, *m1, *p1, *m2, *p2, *x3, *scp;
    float4 *lw1, *lw2;
    float *p1s, *p1q, *p2s, *p2q, *scs, *scq;
    SYM(__half*, fT, g_fT); SYM(__half*, wh, g_wh);
    SYM(__half*, x1, g_x1); SYM(__half*, m1, g_m1); SYM(__half*, p1, g_p1);
    SYM(__half*, m2, g_m2); SYM(__half*, p2, g_p2); SYM(__half*, x3, g_x3);
    SYM(__half*, scp, g_scp);
    SYM(float4*, lw1, g_lw1); SYM(float4*, lw2, g_lw2);
    SYM(float*, p1s, g_p1s); SYM(float*, p1q, g_p1q);
    SYM(float*, p2s, g_p2s); SYM(float*, p2q, g_p2q);
    SYM(float*, scs, g_scs); SYM(float*, scq, g_scq);

    cudaFuncSetAttribute(fused_a_kernel,
                         cudaFuncAttributeMaxDynamicSharedMemorySize, CONV_SMEM);
    cudaFuncSetAttribute(mma_conv_k<128, 256, EPI_STATS, 8>,
                         cudaFuncAttributeMaxDynamicSharedMemorySize, CONV_SMEM);
    cudaFuncSetAttribute(mma_conv_k<256, 256, EPI_STATS, 16>,
                         cudaFuncAttributeMaxDynamicSharedMemorySize, CONV_SMEM);
    cudaFuncSetAttribute(mma_conv_k<512, 256, EPI_FINAL, 32>,
                         cudaFuncAttributeMaxDynamicSharedMemorySize, CONV_SMEM);

    // K1: zero stats + weight convert + feature transpose
    prep_transpose_kernel<<<4096 + 256, 256>>>(w1, pool1_w, pool2_w, sc_w,
                                               mlp2_w, features, fT);
    // K2: mlp1 (y=0) + shortcut conv (y=1..4) + geo moments (y=5)
    fused_a_kernel<<<dim3(Nc / 128, 6, Bc), 256, CONV_SMEM>>>(
        wh, b1, sc_b, fT, x1, scp, scs, scq, coords, knn_idx, knn_dist);
    // K3: closed-form GN for both LSE layers -> prefolded weights
    lse_finalize_kernel<<<dim3(Bc, 2), 128>>>(lse1_w, lse1_b, lse1_gw, lse1_gb,
                                              lse2_w, lse2_b, lse2_gw, lse2_gb);
    // K4: lse1
    lse_apply_kernel<false><<<dim3(Nc / PTS, Bc), 128>>>(
        coords, knn_idx, knn_dist, lw1, x1, m1,
        nullptr, nullptr, nullptr, nullptr);
    // K5: pool1 conv + stats
    mma_conv_k<128, 256, EPI_STATS, 8>
        <<<dim3(Nc / 128, 1, Bc), 256, CONV_SMEM>>>(wh + WOFF_P1, pool1_b, m1, p1,
                                                    nullptr, nullptr, nullptr,
                                                    p1s, p1q);
    // K6: lse2 (inline pool1 GN finalize)
    lse_apply_kernel<true><<<dim3(Nc / PTS, Bc), 128>>>(
        coords, knn_idx, knn_dist, lw2, p1, m2,
        p1s, p1q, pool1_gw, pool1_gb);
    // K7: pool2 conv + stats
    mma_conv_k<256, 256, EPI_STATS, 16>
        <<<dim3(Nc / 128, 2, Bc), 256, CONV_SMEM>>>(wh + WOFF_P2, pool2_b, m2, p2,
                                                    nullptr, nullptr, nullptr,
                                                    p2s, p2q);
    // K8: normalize (inline pool2 GN finalize)
    normalize_h_kernel<<<(Bc * Nc * 256) / 1024, 256>>>(p2, x3, p2s, p2q,
                                                        pool2_gw, pool2_gb);
    // K9: final conv + inline shortcut GN + leaky(0.01) -> out [b][o][n] fp32
    mma_conv_k<512, 256, EPI_FINAL, 32>
        <<<dim3(Nc / 128, 4, Bc), 256, CONV_SMEM>>>(wh + WOFF_M2, mlp2_b, x3, out,
                                                    scp, sc_gw, sc_gb, scs, scq);
}

// round 14
// speedup vs baseline: 1.1526x; 1.0048x over previous
#include <cuda_runtime.h>
#include <cuda_fp16.h>
#include <stdint.h>
#include <math.h>

static constexpr int Bc = 2;
static constexpr int Nc = 16384;
static constexpr int Kc = 16;

// ---------------- scratch ----------------
__device__ __half g_fT[(size_t)Bc * Nc * 128];   // features transposed [b][n][c]
__device__ __half g_wh[311296];                  // all conv weights as fp16
__device__ __half g_x1[(size_t)Bc * Nc * 128];   // mlp1 out  [b][n][c]
__device__ __half g_m1[(size_t)Bc * Nc * 256];   // lse1 pooled mean
__device__ __half g_p1[(size_t)Bc * Nc * 128];   // pool1 pre-GN
__device__ __half g_m2[(size_t)Bc * Nc * 256];   // lse2 pooled mean
__device__ __half g_p2[(size_t)Bc * Nc * 256];   // pool2 pre-GN
__device__ __half g_x3[(size_t)Bc * Nc * 256];   // pool2 out
__device__ __half g_scp[(size_t)Bc * Nc * 512];  // shortcut pre-GN, [b][o][n] fp16

__device__ double g_geoS[Bc * 10];
__device__ double g_geoG[Bc * 55];
__device__ float4 g_lw1[Bc * 128 * 2];   // lse1 prefolded: {a*wc.xyz, cc},{a*wn.xyz, a*wd}
__device__ float4 g_lw2[Bc * 128 * 2];   // lse2 prefolded
__device__ float g_p1s[Bc * 16], g_p1q[Bc * 16];
__device__ float g_p2s[Bc * 16], g_p2q[Bc * 16];
__device__ float g_scs[Bc * 16], g_scq[Bc * 16];

// weight blob offsets (in halves)
static constexpr int WOFF_W1 = 0;
static constexpr int WOFF_P1 = 16384;
static constexpr int WOFF_P2 = 49152;
static constexpr int WOFF_SC = 114688;
static constexpr int WOFF_M2 = 180224;
static constexpr int WTOT = 311296;

// ---------------- helpers ----------------
__device__ __forceinline__ uint32_t smem_u32(const void* p) {
    uint32_t a;
    asm("{ .reg .u64 t; cvta.to.shared.u64 t, %1; cvt.u32.u64 %0, t; }" : "=r"(a) : "l"(p));
    return a;
}
__device__ __forceinline__ void cpa16(uint32_t dst, const void* src) {
    asm volatile("cp.async.cg.shared.global [%0], [%1], 16;" :: "r"(dst), "l"(src));
}
#define CP_COMMIT() asm volatile("cp.async.commit_group;" ::: "memory")
#define CP_WAIT1() asm volatile("cp.async.wait_group 1;" ::: "memory")
#define CP_WAIT0() asm volatile("cp.async.wait_group 0;" ::: "memory")

#define MMA_F16(d, a, b) \
    asm volatile("mma.sync.aligned.m16n8k16.row.col.f32.f16.f16.f32 " \
        "{%0,%1,%2,%3}, {%4,%5,%6,%7}, {%8,%9}, {%0,%1,%2,%3};" \
        : "+f"((d)[0]), "+f"((d)[1]), "+f"((d)[2]), "+f"((d)[3]) \
        : "r"((a)[0]), "r"((a)[1]), "r"((a)[2]), "r"((a)[3]), \
          "r"((b)[0]), "r"((b)[1]))

#define LDSM4(r, addr) \
    asm volatile("ldmatrix.sync.aligned.m8n8.x4.shared.b16 {%0,%1,%2,%3}, [%4];" \
        : "=r"((r)[0]), "=r"((r)[1]), "=r"((r)[2]), "=r"((r)[3]) : "r"(addr))

// swizzled offset within a row-major 128B-row tile: row r, 16B-chunk c (0..7)
__device__ __forceinline__ uint32_t swoff(int r, int c) {
    return (uint32_t)(r * 128 + ((c ^ (r & 7)) << 4));
}

enum { EPI_LEAKY02 = 0, EPI_STATS = 1, EPI_TRANS_STATS = 2, EPI_FINAL = 3 };
static constexpr int CONV_SMEM = 3 * 32768 + 256;
static constexpr int OSH_STRIDE = 136;

// ---------------- K1: zero stats + convert weights + transpose -------------
__global__ __launch_bounds__(256) void prep_transpose_kernel(
    const float* __restrict__ w1, const float* __restrict__ pw1,
    const float* __restrict__ pw2, const float* __restrict__ scw,
    const float* __restrict__ mw,
    const float* __restrict__ features, __half* __restrict__ fT)
{
    __shared__ float t[32][33];
    int bid = blockIdx.x;
    if (bid < 4096) {
        int b = bid >> 11;
        int rem = bid & 2047;
        int cB = (rem >> 9) * 32, nB = (rem & 511) * 32;
        int tx = threadIdx.x & 31, ty = threadIdx.x >> 5;
#pragma unroll
        for (int i = 0; i < 4; ++i)
            t[ty + 8 * i][tx] =
                features[((size_t)b * 128 + cB + ty + 8 * i) * Nc + nB + tx];
        __syncthreads();
#pragma unroll
        for (int i = 0; i < 4; ++i)
            fT[((size_t)b * Nc + nB + ty + 8 * i) * 128 + cB + tx] =
                __float2half(t[tx][ty + 8 * i]);
    } else {
        int cb = bid - 4096;  // 0..255
        if (cb == 0) {
            int tt = threadIdx.x;
            if (tt < Bc * 10) g_geoS[tt] = 0.0;
            if (tt < Bc * 55) g_geoG[tt] = 0.0;
            if (tt < Bc * 16) {
                g_p1s[tt] = 0.f; g_p1q[tt] = 0.f;
                g_p2s[tt] = 0.f; g_p2q[tt] = 0.f;
                g_scs[tt] = 0.f; g_scq[tt] = 0.f;
            }
        }
        for (int i = cb * 256 + threadIdx.x; i < WTOT; i += 256 * 256) {
            float v;
            if (i < WOFF_P1) v = w1[i];
            else if (i < WOFF_P2) v = pw1[i - WOFF_P1];
            else if (i < WOFF_SC) v = pw2[i - WOFF_P2];
            else if (i < WOFF_M2) v = scw[i - WOFF_SC];
            else v = mw[i - WOFF_M2];
            g_wh[i] = __float2half(v);
        }
    }
}

// ---------------- geo moments (device body) ----------------
__device__ void geo_body(const float* __restrict__ coords,
                         const int* __restrict__ knn_idx,
                         const float* __restrict__ knn_dist, int bx, int b)
{
    const float* cb = coords + (size_t)b * Nc * 3;
    float S[10];
    float G[55];
#pragma unroll
    for (int c = 0; c < 10; c++) S[c] = 0.f;
#pragma unroll
    for (int p = 0; p < 55; p++) G[p] = 0.f;

    for (int it = bx * 256 + threadIdx.x; it < Nc * Kc; it += 64 * 256) {
        int n = it >> 4;
        size_t base = ((size_t)b * Nc + n) * Kc + (it & 15);
        float cx = cb[n * 3 + 0], cy = cb[n * 3 + 1], cz = cb[n * 3 + 2];
        int j = knn_idx[base];
        float nx = cb[j * 3 + 0], ny = cb[j * 3 + 1], nz = cb[j * 3 + 2];
        float dd = knn_dist[base];
        float g[10] = {cx, cy, cz, nx, ny, nz, cx - nx, cy - ny, cz - nz, dd};
        int p = 0;
#pragma unroll
        for (int c = 0; c < 10; c++) {
            S[c] += g[c];
#pragma unroll
            for (int d = c; d < 10; d++) G[p++] += g[c] * g[d];
        }
    }
#pragma unroll
    for (int c = 0; c < 10; c++)
        for (int off = 16; off; off >>= 1) S[c] += __shfl_xor_sync(~0u, S[c], off);
#pragma unroll
    for (int p = 0; p < 55; p++)
        for (int off = 16; off; off >>= 1) G[p] += __shfl_xor_sync(~0u, G[p], off);
    if ((threadIdx.x & 31) == 0) {
        for (int c = 0; c < 10; c++) atomicAdd(&g_geoS[b * 10 + c], (double)S[c]);
        for (int p = 0; p < 55; p++) atomicAdd(&g_geoG[b * 55 + p], (double)G[p]);
    }
}

// ---------------- closed-form GN stats (fp32) -> prefolded lse weights -----
__global__ void lse_finalize_kernel(
    const float* __restrict__ w1p, const float* __restrict__ b1p,
    const float* __restrict__ gw1, const float* __restrict__ gb1,
    const float* __restrict__ w2p, const float* __restrict__ b2p,
    const float* __restrict__ gw2, const float* __restrict__ gb2)
{
    int b = blockIdx.x;
    int layer = blockIdx.y;
    const float* w = layer ? w2p : w1p;
    const float* bias = layer ? b2p : b1p;
    const float* gw = layer ? gw2 : gw1;
    const float* gb = layer ? gb2 : gb1;
    float4* lw = layer ? g_lw2 : g_lw1;

    __shared__ float sS[10], sG[55];
    int o = threadIdx.x;  // 128
    if (o < 10) sS[o] = (float)g_geoS[b * 10 + o];
    if (o < 55) sG[o] = (float)g_geoG[b * 55 + o];
    __syncthreads();

    float wr[10];
#pragma unroll
    for (int c = 0; c < 10; c++) wr[c] = w[o * 10 + c];
    float t1 = 0.f;
#pragma unroll
    for (int c = 0; c < 10; c++) t1 += wr[c] * sS[c];
    float t2 = 0.f;
    int p = 0;
#pragma unroll
    for (int c = 0; c < 10; c++)
#pragma unroll
        for (int d = c; d < 10; d++) {
            float ww = wr[c] * wr[d];
            t2 += (c == d ? ww : 2.f * ww) * sG[p];
            p++;
        }
    const float NK = (float)Nc * (float)Kc;
    float bo = bias[o];
    float sum = t1 + bo * NK;
    float sq = t2 + 2.f * bo * t1 + bo * bo * NK;
#pragma unroll
    for (int off = 1; off < 8; off <<= 1) {
        sum += __shfl_xor_sync(~0u, sum, off);
        sq += __shfl_xor_sync(~0u, sq, off);
    }
    float M = 8.f * NK;
    float mean = sum / M;
    float var = fmaxf(sq / M - mean * mean, 0.f);
    float rstd = rsqrtf(var + 1e-6f);
    float a = rstd * gw[o];
    float cc = gb[o] + (bo - mean) * a;
    lw[(b * 128 + o) * 2 + 0] =
        make_float4(a * (wr[0] + wr[6]), a * (wr[1] + wr[7]), a * (wr[2] + wr[8]), cc);
    lw[(b * 128 + o) * 2 + 1] =
        make_float4(a * (wr[3] - wr[6]), a * (wr[4] - wr[7]), a * (wr[5] - wr[8]), a * wr[9]);
}

// ---------------- conv device body: 128n x 128o tile, 64-col K chunks ------
template <int O, int C, int EPI, int GSIZE>
__device__ __forceinline__ void conv_dev(
    char* smem, int n0, int o0, int b,
    const __half* __restrict__ Wh, const float* __restrict__ bias,
    const __half* __restrict__ in, void* __restrict__ outv,
    const __half* __restrict__ scpre,
    const float* __restrict__ scgw, const float* __restrict__ scgb,
    float* gsum, float* gsq)
{
    const uint32_t sb = smem_u32(smem);
    float* ssh = (float*)(smem + 98304);
    float* sqh = ssh + 16;
    float* osf = (float*)smem;
    __half* osh = (__half*)smem;

    const int tid = threadIdx.x;
    const int w = tid >> 5, lane = tid & 31;
    const int wr = w & 1, wc = w >> 1;
    const int t = lane & 3, g = lane >> 2;

    const __half* xbase = in + ((size_t)b * Nc + n0) * C;
    const __half* wbase = Wh + (size_t)o0 * C;

    uint32_t sOff[4];
    const __half* gxp[4];
    const __half* gwp[4];
#pragma unroll
    for (int i = 0; i < 4; ++i) {
        int id = tid + 256 * i;
        int r = id >> 3, c = id & 7;
        sOff[i] = swoff(r, c);
        gxp[i] = xbase + (size_t)r * C + c * 8;
        gwp[i] = wbase + (size_t)r * C + c * 8;
    }

    const int quad = lane >> 3, lr = lane & 7;
    const int raA = (quad & 1) * 8 + lr, caA = quad >> 1;
    const int raB = (quad >> 1) * 8 + lr, caB = quad & 1;
    uint32_t rbA[4], rxA[4];
#pragma unroll
    for (int mi = 0; mi < 4; ++mi) {
        int row = wr * 64 + mi * 16 + raA;
        rbA[mi] = (uint32_t)(row * 128);
        rxA[mi] = (uint32_t)(row & 7);
    }
    uint32_t rbB[2], rxB[2];
#pragma unroll
    for (int oi = 0; oi < 2; ++oi) {
        int row = wc * 32 + oi * 16 + raB;
        rbB[oi] = 16384u + (uint32_t)(row * 128);
        rxB[oi] = (uint32_t)(row & 7);
    }

    float d[4][4][4];
#pragma unroll
    for (int mi = 0; mi < 4; ++mi)
#pragma unroll
        for (int ni = 0; ni < 4; ++ni)
#pragma unroll
            for (int e = 0; e < 4; ++e) d[mi][ni][e] = 0.f;

    constexpr int NCH = C / 64;
    auto stage = [&](int j) {
        uint32_t base = sb + (uint32_t)(j % 3) * 32768u;
        int cc = j * 64;
#pragma unroll
        for (int i = 0; i < 4; ++i) {
            cpa16(base + sOff[i], gxp[i] + cc);
            cpa16(base + 16384 + sOff[i], gwp[i] + cc);
        }
        CP_COMMIT();
    };
    stage(0);
    if (NCH > 1) stage(1);

    for (int j = 0; j < NCH; ++j) {
        if (j + 1 < NCH) CP_WAIT1(); else CP_WAIT0();
        __syncthreads();
        if (j + 2 < NCH) stage(j + 2);
        const uint32_t base = sb + (uint32_t)(j % 3) * 32768u;
#pragma unroll
        for (int kt = 0; kt < 4; ++kt) {
            uint32_t a[4][4], bb[2][4];
#pragma unroll
            for (int mi = 0; mi < 4; ++mi) {
                uint32_t cA = (uint32_t)(kt * 2 + caA) ^ rxA[mi];
                LDSM4(a[mi], base + rbA[mi] + (cA << 4));
            }
#pragma unroll
            for (int oi = 0; oi < 2; ++oi) {
                uint32_t cB = (uint32_t)(kt * 2 + caB) ^ rxB[oi];
                LDSM4(bb[oi], base + rbB[oi] + (cB << 4));
            }
#pragma unroll
            for (int mi = 0; mi < 4; ++mi)
#pragma unroll
                for (int ni = 0; ni < 4; ++ni) {
                    uint32_t bf[2] = {bb[ni >> 1][(ni & 1) * 2],
                                      bb[ni >> 1][(ni & 1) * 2 + 1]};
                    MMA_F16(d[mi][ni], a[mi], bf);
                }
        }
    }

    // ================= epilogues =================
    if constexpr (EPI == EPI_LEAKY02 || EPI == EPI_STATS) {
        __half* out = (__half*)outv;
        __syncthreads();
        if constexpr (EPI == EPI_STATS) {
            if (tid < 16) { ssh[tid] = 0.f; sqh[tid] = 0.f; }
            __syncthreads();
        }
        float js[4] = {0.f, 0.f, 0.f, 0.f}, jq[4] = {0.f, 0.f, 0.f, 0.f};
#pragma unroll
        for (int mi = 0; mi < 4; ++mi) {
            int p = wr * 64 + mi * 16 + g;
#pragma unroll
            for (int ni = 0; ni < 4; ++ni) {
                int ch = wc * 32 + ni * 8 + 2 * t;
                float b0 = bias[o0 + ch], b1 = bias[o0 + ch + 1];
                float v00 = d[mi][ni][0] + b0, v01 = d[mi][ni][1] + b1;
                float v10 = d[mi][ni][2] + b0, v11 = d[mi][ni][3] + b1;
                if constexpr (EPI == EPI_LEAKY02) {
                    v00 = v00 > 0.f ? v00 : 0.2f * v00;
                    v01 = v01 > 0.f ? v01 : 0.2f * v01;
                    v10 = v10 > 0.f ? v10 : 0.2f * v10;
                    v11 = v11 > 0.f ? v11 : 0.2f * v11;
                } else {
                    js[ni] += v00 + v01 + v10 + v11;
                    jq[ni] += v00 * v00 + v01 * v01 + v10 * v10 + v11 * v11;
                }
                *(__half2*)&osh[p * OSH_STRIDE + ch] = __floats2half2_rn(v00, v01);
                *(__half2*)&osh[(p + 8) * OSH_STRIDE + ch] = __floats2half2_rn(v10, v11);
            }
        }
        if constexpr (EPI == EPI_STATS) {
#pragma unroll
            for (int ni = 0; ni < 4; ++ni) {
                int gl = (wc * 32 + ni * 8) / GSIZE;
                atomicAdd(&ssh[gl], js[ni]);
                atomicAdd(&sqh[gl], jq[ni]);
            }
        }
        __syncthreads();
#pragma unroll
        for (int i = 0; i < 8; ++i) {
            int id = tid + 256 * i;
            int row = id >> 4, c16 = id & 15;
            uint4 v = *(uint4*)&osh[row * OSH_STRIDE + c16 * 8];
            *(uint4*)&out[((size_t)b * Nc + n0 + row) * O + o0 + c16 * 8] = v;
        }
        if constexpr (EPI == EPI_STATS) {
            constexpr int NG = 128 / GSIZE;
            if (tid < NG) {
                atomicAdd(&gsum[b * 16 + o0 / GSIZE + tid], ssh[tid]);
                atomicAdd(&gsq[b * 16 + o0 / GSIZE + tid], sqh[tid]);
            }
        }
    } else {
        __syncthreads();
        if (tid < 16) { ssh[tid] = 0.f; sqh[tid] = 0.f; }
        __syncthreads();
#pragma unroll
        for (int p = 0; p < 2; ++p) {
            if ((wc >> 1) == p) {
                float js[4] = {0.f, 0.f, 0.f, 0.f}, jq[4] = {0.f, 0.f, 0.f, 0.f};
#pragma unroll
                for (int mi = 0; mi < 4; ++mi) {
                    int nr = wr * 64 + mi * 16 + g;
#pragma unroll
                    for (int ni = 0; ni < 4; ++ni) {
                        int oc = (wc & 1) * 32 + ni * 8 + 2 * t;
                        float b0 = 0.f, b1 = 0.f;
                        if constexpr (EPI == EPI_TRANS_STATS) {
                            b0 = bias[o0 + p * 64 + oc];
                            b1 = bias[o0 + p * 64 + oc + 1];
                        }
                        float v00 = d[mi][ni][0] + b0, v01 = d[mi][ni][1] + b1;
                        float v10 = d[mi][ni][2] + b0, v11 = d[mi][ni][3] + b1;
                        if constexpr (EPI == EPI_TRANS_STATS) {
                            js[ni] += v00 + v01 + v10 + v11;
                            jq[ni] += v00 * v00 + v01 * v01 + v10 * v10 + v11 * v11;
                        }
                        osf[oc * 132 + nr] = v00;
                        osf[(oc + 1) * 132 + nr] = v01;
                        osf[oc * 132 + nr + 8] = v10;
                        osf[(oc + 1) * 132 + nr + 8] = v11;
                    }
                }
                if constexpr (EPI == EPI_TRANS_STATS) {
#pragma unroll
                    for (int ni = 0; ni < 4; ++ni) {
                        int gl = (p * 64 + (wc & 1) * 32 + ni * 8) / GSIZE;
                        atomicAdd(&ssh[gl], js[ni]);
                        atomicAdd(&sqh[gl], jq[ni]);
                    }
                }
            }
            __syncthreads();
#pragma unroll
            for (int rr = 0; rr < 8; ++rr) {
                int r = w + rr * 8;
                int og = o0 + p * 64 + r;
                float4 v = *(float4*)&osf[r * 132 + lane * 4];
                if constexpr (EPI == EPI_FINAL) {
                    float* op = (float*)outv + ((size_t)b * O + og) * Nc + n0;
                    float bi = bias[og];
                    const float Minv = 1.f / (GSIZE * (float)Nc);
                    int gg = og / GSIZE;
                    float mean = gsum[b * 16 + gg] * Minv;
                    float var = fmaxf(gsq[b * 16 + gg] * Minv - mean * mean, 0.f);
                    float rstd = rsqrtf(var + 1e-6f);
                    float av = rstd * scgw[og];
                    float cv = scgb[og] - mean * av;
                    uint2 sraw = *(const uint2*)(scpre +
                        ((size_t)b * O + og) * Nc + n0 + lane * 4);
                    float2 s0 = __half22float2(*(__half2*)&sraw.x);
                    float2 s1 = __half22float2(*(__half2*)&sraw.y);
                    float ss[4] = {s0.x, s0.y, s1.x, s1.y};
                    float4 rrv;
#pragma unroll
                    for (int e = 0; e < 4; ++e) {
                        float x = (&v.x)[e] + bi + fmaf(ss[e], av, cv);
                        (&rrv.x)[e] = x > 0.f ? x : 0.01f * x;
                    }
                    *(float4*)(op + lane * 4) = rrv;
                } else {
                    __half* op = (__half*)outv + ((size_t)b * O + og) * Nc + n0;
                    uint2 st;
                    *(__half2*)&st.x = __floats2half2_rn(v.x, v.y);
                    *(__half2*)&st.y = __floats2half2_rn(v.z, v.w);
                    *(uint2*)(op + lane * 4) = st;
                }
            }
            __syncthreads();
        }
        if constexpr (EPI == EPI_TRANS_STATS) {
            constexpr int NG = 128 / GSIZE;
            if (tid < NG) {
                atomicAdd(&gsum[b * 16 + o0 / GSIZE + tid], ssh[tid]);
                atomicAdd(&gsq[b * 16 + o0 / GSIZE + tid], sqh[tid]);
            }
        }
    }
}

// ---------------- standalone conv kernels ----------------------------------
template <int O, int C, int EPI, int GSIZE>
__global__ __launch_bounds__(256, 2) void mma_conv_k(
    const __half* __restrict__ Wh, const float* __restrict__ bias,
    const __half* __restrict__ in, void* __restrict__ outv,
    const __half* __restrict__ scpre,
    const float* __restrict__ scgw, const float* __restrict__ scgb,
    float* gsum, float* gsq)
{
    extern __shared__ __align__(16) char smem[];
    conv_dev<O, C, EPI, GSIZE>(smem, blockIdx.x * 128, blockIdx.y * 128,
                               blockIdx.z, Wh, bias, in, outv,
                               scpre, scgw, scgb, gsum, gsq);
}

// ---------------- K2: mlp1 + shortcut conv + geo moments -------------------
__global__ __launch_bounds__(256, 2) void fused_a_kernel(
    const __half* __restrict__ wh, const float* __restrict__ b1,
    const float* __restrict__ sc_b, const __half* __restrict__ fT,
    __half* __restrict__ x1, __half* __restrict__ scp,
    float* scs, float* scq,
    const float* __restrict__ coords, const int* __restrict__ knn_idx,
    const float* __restrict__ knn_dist)
{
    extern __shared__ __align__(16) char smem[];
    int y = blockIdx.y, b = blockIdx.z;
    if (y == 5) {
        if (blockIdx.x < 64) geo_body(coords, knn_idx, knn_dist, blockIdx.x, b);
        return;
    }
    if (y == 0)
        conv_dev<128, 128, EPI_LEAKY02, 8>(smem, blockIdx.x * 128, 0, b,
            wh + WOFF_W1, b1, fT, x1, nullptr, nullptr, nullptr, nullptr, nullptr);
    else
        conv_dev<512, 128, EPI_TRANS_STATS, 32>(smem, blockIdx.x * 128,
            (y - 1) * 128, b, wh + WOFF_SC, sc_b, fT, scp,
            nullptr, nullptr, nullptr, scs, scq);
}

// ---------------- normalize p2 -> x3 with inline fin2 ----------------------
__global__ __launch_bounds__(256) void normalize_h_kernel(
    const __half* __restrict__ p, __half* __restrict__ x,
    const float* __restrict__ sums, const float* __restrict__ sqs,
    const float* __restrict__ gw, const float* __restrict__ gb)
{
    size_t i = ((size_t)blockIdx.x * blockDim.x + threadIdx.x) * 4;
    int c = (int)(i % 256);
    int b = (int)(i / ((size_t)Nc * 256));
    const float Minv = 1.f / (16.f * Nc);
    int g = c >> 4;
    float mean = sums[b * 16 + g] * Minv;
    float var = fmaxf(sqs[b * 16 + g] * Minv - mean * mean, 0.f);
    float rstd = rsqrtf(var + 1e-6f);
    __half2 v0 = *(const __half2*)(p + i);
    __half2 v1 = *(const __half2*)(p + i + 2);
    float vv[4] = {__half2float(v0.x), __half2float(v0.y),
                   __half2float(v1.x), __half2float(v1.y)};
    float rr[4];
#pragma unroll
    for (int e = 0; e < 4; ++e) {
        float a = rstd * gw[c + e];
        float cc = gb[c + e] - mean * a;
        rr[e] = fmaxf(fmaf(vv[e], a, cc), 0.f);
    }
    *(__half2*)(x + i) = __floats2half2_rn(rr[0], rr[1]);
    *(__half2*)(x + i + 2) = __floats2half2_rn(rr[2], rr[3]);
}

// ---------------- fused LSE (byte-offset gather; prefolded geo weights) -----
static constexpr int PTS = 8;
template <bool AFF>
__global__ __launch_bounds__(128) void lse_apply_kernel(
    const float* __restrict__ coords, const int* __restrict__ knn_idx,
    const float* __restrict__ knn_dist, const float4* __restrict__ lw,
    const __half* __restrict__ xsrc, __half* __restrict__ mout,
    const float* __restrict__ sums, const float* __restrict__ sqs,
    const float* __restrict__ pgw, const float* __restrict__ pgb)
{
    __shared__ int sh_off[PTS * 16];    // j * 256 (byte offset into [n][c] rows)
    __shared__ float4 sh_g[PTS * 16];   // nbr.xyz, dist
    __shared__ float sh_ctr[PTS][3];
    __shared__ float2 spart[PTS][64];

    const int b = blockIdx.y;
    const int n0 = blockIdx.x * PTS;
    const int tid = threadIdx.x;
    const float* cb = coords + (size_t)b * Nc * 3;

    float ddv;
    int jv = 0;
    if (tid < PTS * 16) {
        size_t base = ((size_t)b * Nc + n0) * 16 + tid;
        jv = knn_idx[base];
        sh_off[tid] = jv << 8;  // j * 128 halves * 2 bytes
        ddv = knn_dist[base];
    }
    if (tid < PTS * 3) sh_ctr[tid / 3][tid % 3] = cb[n0 * 3 + tid];
    __syncthreads();
    if (tid < PTS * 16) {
        sh_g[tid] = make_float4(cb[jv * 3 + 0], cb[jv * 3 + 1], cb[jv * 3 + 2], ddv);
    }
    // prefolded weights: f0 = {a*wc.xyz, cc}, f1 = {a*wn.xyz, a*wd}
    const float4 f0 = lw[(b * 128 + tid) * 2 + 0];
    const float4 f1 = lw[(b * 128 + tid) * 2 + 1];

    const int cp = tid & 63, h = tid >> 6;
    float an0 = 0.f, an1 = 0.f, cn0 = 0.f, cn1 = 0.f;
    if (AFF) {
        const float Minv = 1.f / (8.f * Nc);
        int ch0 = 2 * cp;
        int g = ch0 >> 3;
        float mean = sums[b * 16 + g] * Minv;
        float var = fmaxf(sqs[b * 16 + g] * Minv - mean * mean, 0.f);
        float rstd = rsqrtf(var + 1e-6f);
        an0 = rstd * pgw[ch0];
        cn0 = pgb[ch0] - mean * an0;
        an1 = rstd * pgw[ch0 + 1];
        cn1 = pgb[ch0 + 1] - mean * an1;
    }
    // base byte pointer for this thread's channel pair
    const char* xbp = (const char*)(xsrc + (size_t)b * Nc * 128) + 4 * cp;
    __half* mo = mout + ((size_t)b * Nc + n0) * 256;
    __syncthreads();

    float2 accn[PTS];
#pragma unroll
    for (int pi = 0; pi < PTS; pi++) {
        float dotc = fmaf(f0.x, sh_ctr[pi][0],
                     fmaf(f0.y, sh_ctr[pi][1],
                     fmaf(f0.z, sh_ctr[pi][2], f0.w)));
        float accg = 0.f;
#pragma unroll
        for (int k = 0; k < 16; k++) {
            float4 gv = sh_g[pi * 16 + k];
            float dot = fmaf(f1.x, gv.x, fmaf(f1.y, gv.y,
                        fmaf(f1.z, gv.z, fmaf(f1.w, gv.w, dotc))));
            accg += fmaxf(dot, 0.f);
        }
        mo[(size_t)pi * 256 + tid] = __float2half(accg * 0.0625f);

        float2 acc = make_float2(0.f, 0.f);
        const int sb0 = pi * 16 + h * 8;
#pragma unroll
        for (int k = 0; k < 8; k++) {
            int off = sh_off[sb0 + k];
            float2 f = __half22float2(*(const __half2*)(xbp + off));
            if (AFF) {
                f.x = fmaxf(fmaf(f.x, an0, cn0), 0.f);
                f.y = fmaxf(fmaf(f.y, an1, cn1), 0.f);
            }
            acc.x += f.x; acc.y += f.y;
        }
        if (h == 1) spart[pi][cp] = acc;
        accn[pi] = acc;
    }
    __syncthreads();
    if (h == 0) {
#pragma unroll
        for (int pi = 0; pi < PTS; pi++) {
            float2 o = spart[pi][cp];
            o.x = (o.x + accn[pi].x) * 0.0625f;
            o.y = (o.y + accn[pi].y) * 0.0625f;
            *(__half2*)&mo[(size_t)pi * 256 + 128 + 2 * cp] =
                __floats2half2_rn(o.x, o.y);
        }
    }
}

// ---------------- host ----------------
#define SYM(ty, p, s) do { void* _t; cudaGetSymbolAddress(&_t, s); p = (ty)_t; } while (0)

extern "C" void kernel_launch(void* const* d_in, const int* in_sizes, int n_in,
                              void* d_out, int out_size)
{
    (void)in_sizes; (void)n_in; (void)out_size;
    const float* coords   = (const float*)d_in[0];
    const float* features = (const float*)d_in[1];
    const float* knn_dist = (const float*)d_in[2];
    const int*   knn_idx  = (const int*)d_in[3];
    const float* w1       = (const float*)d_in[4];
    const float* b1       = (const float*)d_in[5];
    const float* lse1_w   = (const float*)d_in[6];
    const float* lse1_b   = (const float*)d_in[7];
    const float* lse1_gw  = (const float*)d_in[8];
    const float* lse1_gb  = (const float*)d_in[9];
    const float* pool1_w  = (const float*)d_in[10];
    const float* pool1_b  = (const float*)d_in[11];
    const float* pool1_gw = (const float*)d_in[12];
    const float* pool1_gb = (const float*)d_in[13];
    const float* lse2_w   = (const float*)d_in[14];
    const float* lse2_b   = (const float*)d_in[15];
    const float* lse2_gw  = (const float*)d_in[16];
    const float* lse2_gb  = (const float*)d_in[17];
    const float* pool2_w  = (const float*)d_in[18];
    const float* pool2_b  = (const float*)d_in[19];
    const float* pool2_gw = (const float*)d_in[20];
    const float* pool2_gb = (const float*)d_in[21];
    const float* mlp2_w   = (const float*)d_in[22];
    const float* mlp2_b   = (const float*)d_in[23];
    const float* sc_w     = (const float*)d_in[24];
    const float* sc_b     = (const float*)d_in[25];
    const float* sc_gw    = (const float*)d_in[26];
    const float* sc_gb    = (const float*)d_in[27];
    float* out = (float*)d_out;

    __half *fT, *wh, *x1, *m1, *p1, *m2, *p2, *x3, *scp;
    float4 *lw1, *lw2;
    float *p1s, *p1q, *p2s, *p2q, *scs, *scq;
    SYM(__half*, fT, g_fT); SYM(__half*, wh, g_wh);
    SYM(__half*, x1, g_x1); SYM(__half*, m1, g_m1); SYM(__half*, p1, g_p1);
    SYM(__half*, m2, g_m2); SYM(__half*, p2, g_p2); SYM(__half*, x3, g_x3);
    SYM(__half*, scp, g_scp);
    SYM(float4*, lw1, g_lw1); SYM(float4*, lw2, g_lw2);
    SYM(float*, p1s, g_p1s); SYM(float*, p1q, g_p1q);
    SYM(float*, p2s, g_p2s); SYM(float*, p2q, g_p2q);
    SYM(float*, scs, g_scs); SYM(float*, scq, g_scq);

    cudaFuncSetAttribute(fused_a_kernel,
                         cudaFuncAttributeMaxDynamicSharedMemorySize, CONV_SMEM);
    cudaFuncSetAttribute(mma_conv_k<128, 256, EPI_STATS, 8>,
                         cudaFuncAttributeMaxDynamicSharedMemorySize, CONV_SMEM);
    cudaFuncSetAttribute(mma_conv_k<256, 256, EPI_STATS, 16>,
                         cudaFuncAttributeMaxDynamicSharedMemorySize, CONV_SMEM);
    cudaFuncSetAttribute(mma_conv_k<512, 256, EPI_FINAL, 32>,
                         cudaFuncAttributeMaxDynamicSharedMemorySize, CONV_SMEM);

    // K1: zero stats + weight convert + feature transpose
    prep_transpose_kernel<<<4096 + 256, 256>>>(w1, pool1_w, pool2_w, sc_w,
                                               mlp2_w, features, fT);
    // K2: mlp1 (y=0) + shortcut conv (y=1..4) + geo moments (y=5)
    fused_a_kernel<<<dim3(Nc / 128, 6, Bc), 256, CONV_SMEM>>>(
        wh, b1, sc_b, fT, x1, scp, scs, scq, coords, knn_idx, knn_dist);
    // K3: closed-form GN for both LSE layers -> prefolded weights
    lse_finalize_kernel<<<dim3(Bc, 2), 128>>>(lse1_w, lse1_b, lse1_gw, lse1_gb,
                                              lse2_w, lse2_b, lse2_gw, lse2_gb);
    // K4: lse1
    lse_apply_kernel<false><<<dim3(Nc / PTS, Bc), 128>>>(
        coords, knn_idx, knn_dist, lw1, x1, m1,
        nullptr, nullptr, nullptr, nullptr);
    // K5: pool1 conv + stats
    mma_conv_k<128, 256, EPI_STATS, 8>
        <<<dim3(Nc / 128, 1, Bc), 256, CONV_SMEM>>>(wh + WOFF_P1, pool1_b, m1, p1,
                                                    nullptr, nullptr, nullptr,
                                                    p1s, p1q);
    // K6: lse2 (inline pool1 GN finalize)
    lse_apply_kernel<true><<<dim3(Nc / PTS, Bc), 128>>>(
        coords, knn_idx, knn_dist, lw2, p1, m2,
        p1s, p1q, pool1_gw, pool1_gb);
    // K7: pool2 conv + stats
    mma_conv_k<256, 256, EPI_STATS, 16>
        <<<dim3(Nc / 128, 2, Bc), 256, CONV_SMEM>>>(wh + WOFF_P2, pool2_b, m2, p2,
                                                    nullptr, nullptr, nullptr,
                                                    p2s, p2q);
    // K8: normalize (inline pool2 GN finalize)
    normalize_h_kernel<<<(Bc * Nc * 256) / 1024, 256>>>(p2, x3, p2s, p2q,
                                                        pool2_gw, pool2_gb);
    // K9: final conv + inline shortcut GN + leaky(0.01) -> out [b][o][n] fp32
    mma_conv_k<512, 256, EPI_FINAL, 32>
        <<<dim3(Nc / 128, 4, Bc), 256, CONV_SMEM>>>(wh + WOFF_M2, mlp2_b, x3, out,
                                                    scp, sc_gw, sc_gb, scs, scq);
}

// round 16
// speedup vs baseline: 1.1699x; 1.0150x over previous
#include <cuda_runtime.h>
#include <cuda_fp16.h>
#include <stdint.h>
#include <math.h>

static constexpr int Bc = 2;
static constexpr int Nc = 16384;
static constexpr int Kc = 16;

// ---------------- scratch ----------------
__device__ __half g_fT[(size_t)Bc * Nc * 128];
__device__ __half g_wh[311296];
__device__ __half g_x1[(size_t)Bc * Nc * 128];
__device__ __half g_m1[(size_t)Bc * Nc * 256];
__device__ __half g_p1[(size_t)Bc * Nc * 128];
__device__ __half g_m2[(size_t)Bc * Nc * 256];
__device__ __half g_p2[(size_t)Bc * Nc * 256];
__device__ __half g_x3[(size_t)Bc * Nc * 256];
__device__ __half g_scp[(size_t)Bc * Nc * 512];

__device__ double g_geoS[Bc * 10];
__device__ double g_geoG[Bc * 55];
__device__ float4 g_lw1[Bc * 128 * 2];
__device__ float4 g_lw2[Bc * 128 * 2];
__device__ float g_p1s[Bc * 16], g_p1q[Bc * 16];
__device__ float g_p2s[Bc * 16], g_p2q[Bc * 16];
__device__ float g_scs[Bc * 16], g_scq[Bc * 16];

static constexpr int WOFF_W1 = 0;
static constexpr int WOFF_P1 = 16384;
static constexpr int WOFF_P2 = 49152;
static constexpr int WOFF_SC = 114688;
static constexpr int WOFF_M2 = 180224;
static constexpr int WTOT = 311296;

// ---------------- helpers ----------------
__device__ __forceinline__ uint32_t smem_u32(const void* p) {
    uint32_t a;
    asm("{ .reg .u64 t; cvta.to.shared.u64 t, %1; cvt.u32.u64 %0, t; }" : "=r"(a) : "l"(p));
    return a;
}
__device__ __forceinline__ void cpa16(uint32_t dst, const void* src) {
    asm volatile("cp.async.cg.shared.global [%0], [%1], 16;" :: "r"(dst), "l"(src));
}
#define CP_COMMIT() asm volatile("cp.async.commit_group;" ::: "memory")
#define CP_WAIT1() asm volatile("cp.async.wait_group 1;" ::: "memory")
#define CP_WAIT0() asm volatile("cp.async.wait_group 0;" ::: "memory")

#define MMA_F16(d, a, b) \
    asm volatile("mma.sync.aligned.m16n8k16.row.col.f32.f16.f16.f32 " \
        "{%0,%1,%2,%3}, {%4,%5,%6,%7}, {%8,%9}, {%0,%1,%2,%3};" \
        : "+f"((d)[0]), "+f"((d)[1]), "+f"((d)[2]), "+f"((d)[3]) \
        : "r"((a)[0]), "r"((a)[1]), "r"((a)[2]), "r"((a)[3]), \
          "r"((b)[0]), "r"((b)[1]))

#define LDSM4(r, addr) \
    asm volatile("ldmatrix.sync.aligned.m8n8.x4.shared.b16 {%0,%1,%2,%3}, [%4];" \
        : "=r"((r)[0]), "=r"((r)[1]), "=r"((r)[2]), "=r"((r)[3]) : "r"(addr))

__device__ __forceinline__ uint32_t swoff(int r, int c) {
    return (uint32_t)(r * 128 + ((c ^ (r & 7)) << 4));
}

enum { EPI_LEAKY02 = 0, EPI_STATS = 1, EPI_TRANS_STATS = 2, EPI_FINAL = 3 };
static constexpr int CONV_SMEM = 3 * 32768 + 256;
static constexpr int OSH_STRIDE = 136;

// ---------------- K1: zero stats + convert weights + transpose -------------
__global__ __launch_bounds__(256) void prep_transpose_kernel(
    const float* __restrict__ w1, const float* __restrict__ pw1,
    const float* __restrict__ pw2, const float* __restrict__ scw,
    const float* __restrict__ mw,
    const float* __restrict__ features, __half* __restrict__ fT)
{
    __shared__ float t[32][33];
    int bid = blockIdx.x;
    if (bid < 4096) {
        int b = bid >> 11;
        int rem = bid & 2047;
        int cB = (rem >> 9) * 32, nB = (rem & 511) * 32;
        int tx = threadIdx.x & 31, ty = threadIdx.x >> 5;
#pragma unroll
        for (int i = 0; i < 4; ++i)
            t[ty + 8 * i][tx] =
                features[((size_t)b * 128 + cB + ty + 8 * i) * Nc + nB + tx];
        __syncthreads();
#pragma unroll
        for (int i = 0; i < 4; ++i)
            fT[((size_t)b * Nc + nB + ty + 8 * i) * 128 + cB + tx] =
                __float2half(t[tx][ty + 8 * i]);
    } else {
        int cb = bid - 4096;
        if (cb == 0) {
            int tt = threadIdx.x;
            if (tt < Bc * 10) g_geoS[tt] = 0.0;
            if (tt < Bc * 55) g_geoG[tt] = 0.0;
            if (tt < Bc * 16) {
                g_p1s[tt] = 0.f; g_p1q[tt] = 0.f;
                g_p2s[tt] = 0.f; g_p2q[tt] = 0.f;
                g_scs[tt] = 0.f; g_scq[tt] = 0.f;
            }
        }
        for (int i = cb * 256 + threadIdx.x; i < WTOT; i += 256 * 256) {
            float v;
            if (i < WOFF_P1) v = w1[i];
            else if (i < WOFF_P2) v = pw1[i - WOFF_P1];
            else if (i < WOFF_SC) v = pw2[i - WOFF_P2];
            else if (i < WOFF_M2) v = scw[i - WOFF_SC];
            else v = mw[i - WOFF_M2];
            g_wh[i] = __float2half(v);
        }
    }
}

// ---------------- geo moments (device body) ----------------
__device__ void geo_body(const float* __restrict__ coords,
                         const int* __restrict__ knn_idx,
                         const float* __restrict__ knn_dist, int bx, int b)
{
    const float* cb = coords + (size_t)b * Nc * 3;
    float S[10];
    float G[55];
#pragma unroll
    for (int c = 0; c < 10; c++) S[c] = 0.f;
#pragma unroll
    for (int p = 0; p < 55; p++) G[p] = 0.f;

    for (int it = bx * 256 + threadIdx.x; it < Nc * Kc; it += 64 * 256) {
        int n = it >> 4;
        size_t base = ((size_t)b * Nc + n) * Kc + (it & 15);
        float cx = cb[n * 3 + 0], cy = cb[n * 3 + 1], cz = cb[n * 3 + 2];
        int j = knn_idx[base];
        float nx = cb[j * 3 + 0], ny = cb[j * 3 + 1], nz = cb[j * 3 + 2];
        float dd = knn_dist[base];
        float g[10] = {cx, cy, cz, nx, ny, nz, cx - nx, cy - ny, cz - nz, dd};
        int p = 0;
#pragma unroll
        for (int c = 0; c < 10; c++) {
            S[c] += g[c];
#pragma unroll
            for (int d = c; d < 10; d++) G[p++] += g[c] * g[d];
        }
    }
#pragma unroll
    for (int c = 0; c < 10; c++)
        for (int off = 16; off; off >>= 1) S[c] += __shfl_xor_sync(~0u, S[c], off);
#pragma unroll
    for (int p = 0; p < 55; p++)
        for (int off = 16; off; off >>= 1) G[p] += __shfl_xor_sync(~0u, G[p], off);
    if ((threadIdx.x & 31) == 0) {
        for (int c = 0; c < 10; c++) atomicAdd(&g_geoS[b * 10 + c], (double)S[c]);
        for (int p = 0; p < 55; p++) atomicAdd(&g_geoG[b * 55 + p], (double)G[p]);
    }
}

// ---------------- closed-form GN stats (fp32) -> prefolded lse weights -----
__global__ void lse_finalize_kernel(
    const float* __restrict__ w1p, const float* __restrict__ b1p,
    const float* __restrict__ gw1, const float* __restrict__ gb1,
    const float* __restrict__ w2p, const float* __restrict__ b2p,
    const float* __restrict__ gw2, const float* __restrict__ gb2)
{
    int b = blockIdx.x;
    int layer = blockIdx.y;
    const float* w = layer ? w2p : w1p;
    const float* bias = layer ? b2p : b1p;
    const float* gw = layer ? gw2 : gw1;
    const float* gb = layer ? gb2 : gb1;
    float4* lw = layer ? g_lw2 : g_lw1;

    __shared__ float sS[10], sG[55];
    int o = threadIdx.x;
    if (o < 10) sS[o] = (float)g_geoS[b * 10 + o];
    if (o < 55) sG[o] = (float)g_geoG[b * 55 + o];
    __syncthreads();

    float wr[10];
#pragma unroll
    for (int c = 0; c < 10; c++) wr[c] = w[o * 10 + c];
    float t1 = 0.f;
#pragma unroll
    for (int c = 0; c < 10; c++) t1 += wr[c] * sS[c];
    float t2 = 0.f;
    int p = 0;
#pragma unroll
    for (int c = 0; c < 10; c++)
#pragma unroll
        for (int d = c; d < 10; d++) {
            float ww = wr[c] * wr[d];
            t2 += (c == d ? ww : 2.f * ww) * sG[p];
            p++;
        }
    const float NK = (float)Nc * (float)Kc;
    float bo = bias[o];
    float sum = t1 + bo * NK;
    float sq = t2 + 2.f * bo * t1 + bo * bo * NK;
#pragma unroll
    for (int off = 1; off < 8; off <<= 1) {
        sum += __shfl_xor_sync(~0u, sum, off);
        sq += __shfl_xor_sync(~0u, sq, off);
    }
    float M = 8.f * NK;
    float mean = sum / M;
    float var = fmaxf(sq / M - mean * mean, 0.f);
    float rstd = rsqrtf(var + 1e-6f);
    float a = rstd * gw[o];
    float cc = gb[o] + (bo - mean) * a;
    lw[(b * 128 + o) * 2 + 0] =
        make_float4(a * (wr[0] + wr[6]), a * (wr[1] + wr[7]), a * (wr[2] + wr[8]), cc);
    lw[(b * 128 + o) * 2 + 1] =
        make_float4(a * (wr[3] - wr[6]), a * (wr[4] - wr[7]), a * (wr[5] - wr[8]), a * wr[9]);
}

// ---------------- conv device body: 128n x 128o tile, 64-col K chunks ------
template <int O, int C, int EPI, int GSIZE>
__device__ __forceinline__ void conv_dev(
    char* smem, int n0, int o0, int b,
    const __half* __restrict__ Wh, const float* __restrict__ bias,
    const __half* __restrict__ in, void* __restrict__ outv,
    const __half* __restrict__ scpre,
    const float* __restrict__ scgw, const float* __restrict__ scgb,
    float* gsum, float* gsq)
{
    const uint32_t sb = smem_u32(smem);
    float* ssh = (float*)(smem + 98304);
    float* sqh = ssh + 16;
    float* osf = (float*)smem;
    __half* osh = (__half*)smem;

    const int tid = threadIdx.x;
    const int w = tid >> 5, lane = tid & 31;
    const int wr = w & 1, wc = w >> 1;
    const int t = lane & 3, g = lane >> 2;

    const __half* xbase = in + ((size_t)b * Nc + n0) * C;
    const __half* wbase = Wh + (size_t)o0 * C;

    uint32_t sOff[4];
    const __half* gxp[4];
    const __half* gwp[4];
#pragma unroll
    for (int i = 0; i < 4; ++i) {
        int id = tid + 256 * i;
        int r = id >> 3, c = id & 7;
        sOff[i] = swoff(r, c);
        gxp[i] = xbase + (size_t)r * C + c * 8;
        gwp[i] = wbase + (size_t)r * C + c * 8;
    }

    const int quad = lane >> 3, lr = lane & 7;
    const int raA = (quad & 1) * 8 + lr, caA = quad >> 1;
    const int raB = (quad >> 1) * 8 + lr, caB = quad & 1;
    uint32_t rbA[4], rxA[4];
#pragma unroll
    for (int mi = 0; mi < 4; ++mi) {
        int row = wr * 64 + mi * 16 + raA;
        rbA[mi] = (uint32_t)(row * 128);
        rxA[mi] = (uint32_t)(row & 7);
    }
    uint32_t rbB[2], rxB[2];
#pragma unroll
    for (int oi = 0; oi < 2; ++oi) {
        int row = wc * 32 + oi * 16 + raB;
        rbB[oi] = 16384u + (uint32_t)(row * 128);
        rxB[oi] = (uint32_t)(row & 7);
    }

    float d[4][4][4];
#pragma unroll
    for (int mi = 0; mi < 4; ++mi)
#pragma unroll
        for (int ni = 0; ni < 4; ++ni)
#pragma unroll
            for (int e = 0; e < 4; ++e) d[mi][ni][e] = 0.f;

    constexpr int NCH = C / 64;
    auto stage = [&](int j) {
        uint32_t base = sb + (uint32_t)(j % 3) * 32768u;
        int cc = j * 64;
#pragma unroll
        for (int i = 0; i < 4; ++i) {
            cpa16(base + sOff[i], gxp[i] + cc);
            cpa16(base + 16384 + sOff[i], gwp[i] + cc);
        }
        CP_COMMIT();
    };
    stage(0);
    if (NCH > 1) stage(1);

    for (int j = 0; j < NCH; ++j) {
        if (j + 1 < NCH) CP_WAIT1(); else CP_WAIT0();
        __syncthreads();
        if (j + 2 < NCH) stage(j + 2);
        const uint32_t base = sb + (uint32_t)(j % 3) * 32768u;
#pragma unroll
        for (int kt = 0; kt < 4; ++kt) {
            uint32_t a[4][4], bb[2][4];
#pragma unroll
            for (int mi = 0; mi < 4; ++mi) {
                uint32_t cA = (uint32_t)(kt * 2 + caA) ^ rxA[mi];
                LDSM4(a[mi], base + rbA[mi] + (cA << 4));
            }
#pragma unroll
            for (int oi = 0; oi < 2; ++oi) {
                uint32_t cB = (uint32_t)(kt * 2 + caB) ^ rxB[oi];
                LDSM4(bb[oi], base + rbB[oi] + (cB << 4));
            }
#pragma unroll
            for (int mi = 0; mi < 4; ++mi)
#pragma unroll
                for (int ni = 0; ni < 4; ++ni) {
                    uint32_t bf[2] = {bb[ni >> 1][(ni & 1) * 2],
                                      bb[ni >> 1][(ni & 1) * 2 + 1]};
                    MMA_F16(d[mi][ni], a[mi], bf);
                }
        }
    }

    // ================= epilogues =================
    if constexpr (EPI == EPI_LEAKY02 || EPI == EPI_STATS) {
        __half* out = (__half*)outv;
        __syncthreads();
        if constexpr (EPI == EPI_STATS) {
            if (tid < 16) { ssh[tid] = 0.f; sqh[tid] = 0.f; }
            __syncthreads();
        }
        float js[4] = {0.f, 0.f, 0.f, 0.f}, jq[4] = {0.f, 0.f, 0.f, 0.f};
#pragma unroll
        for (int mi = 0; mi < 4; ++mi) {
            int p = wr * 64 + mi * 16 + g;
#pragma unroll
            for (int ni = 0; ni < 4; ++ni) {
                int ch = wc * 32 + ni * 8 + 2 * t;
                float b0 = bias[o0 + ch], b1 = bias[o0 + ch + 1];
                float v00 = d[mi][ni][0] + b0, v01 = d[mi][ni][1] + b1;
                float v10 = d[mi][ni][2] + b0, v11 = d[mi][ni][3] + b1;
                if constexpr (EPI == EPI_LEAKY02) {
                    v00 = v00 > 0.f ? v00 : 0.2f * v00;
                    v01 = v01 > 0.f ? v01 : 0.2f * v01;
                    v10 = v10 > 0.f ? v10 : 0.2f * v10;
                    v11 = v11 > 0.f ? v11 : 0.2f * v11;
                } else {
                    js[ni] += v00 + v01 + v10 + v11;
                    jq[ni] += v00 * v00 + v01 * v01 + v10 * v10 + v11 * v11;
                }
                *(__half2*)&osh[p * OSH_STRIDE + ch] = __floats2half2_rn(v00, v01);
                *(__half2*)&osh[(p + 8) * OSH_STRIDE + ch] = __floats2half2_rn(v10, v11);
            }
        }
        if constexpr (EPI == EPI_STATS) {
#pragma unroll
            for (int ni = 0; ni < 4; ++ni) {
                int gl = (wc * 32 + ni * 8) / GSIZE;
                atomicAdd(&ssh[gl], js[ni]);
                atomicAdd(&sqh[gl], jq[ni]);
            }
        }
        __syncthreads();
#pragma unroll
        for (int i = 0; i < 8; ++i) {
            int id = tid + 256 * i;
            int row = id >> 4, c16 = id & 15;
            uint4 v = *(uint4*)&osh[row * OSH_STRIDE + c16 * 8];
            *(uint4*)&out[((size_t)b * Nc + n0 + row) * O + o0 + c16 * 8] = v;
        }
        if constexpr (EPI == EPI_STATS) {
            constexpr int NG = 128 / GSIZE;
            if (tid < NG) {
                atomicAdd(&gsum[b * 16 + o0 / GSIZE + tid], ssh[tid]);
                atomicAdd(&gsq[b * 16 + o0 / GSIZE + tid], sqh[tid]);
            }
        }
    } else {
        __syncthreads();
        if (tid < 16) { ssh[tid] = 0.f; sqh[tid] = 0.f; }
        __syncthreads();
#pragma unroll
        for (int p = 0; p < 2; ++p) {
            if ((wc >> 1) == p) {
                float js[4] = {0.f, 0.f, 0.f, 0.f}, jq[4] = {0.f, 0.f, 0.f, 0.f};
#pragma unroll
                for (int mi = 0; mi < 4; ++mi) {
                    int nr = wr * 64 + mi * 16 + g;
#pragma unroll
                    for (int ni = 0; ni < 4; ++ni) {
                        int oc = (wc & 1) * 32 + ni * 8 + 2 * t;
                        float b0 = 0.f, b1 = 0.f;
                        if constexpr (EPI == EPI_TRANS_STATS) {
                            b0 = bias[o0 + p * 64 + oc];
                            b1 = bias[o0 + p * 64 + oc + 1];
                        }
                        float v00 = d[mi][ni][0] + b0, v01 = d[mi][ni][1] + b1;
                        float v10 = d[mi][ni][2] + b0, v11 = d[mi][ni][3] + b1;
                        if constexpr (EPI == EPI_TRANS_STATS) {
                            js[ni] += v00 + v01 + v10 + v11;
                            jq[ni] += v00 * v00 + v01 * v01 + v10 * v10 + v11 * v11;
                        }
                        osf[oc * 132 + nr] = v00;
                        osf[(oc + 1) * 132 + nr] = v01;
                        osf[oc * 132 + nr + 8] = v10;
                        osf[(oc + 1) * 132 + nr + 8] = v11;
                    }
                }
                if constexpr (EPI == EPI_TRANS_STATS) {
#pragma unroll
                    for (int ni = 0; ni < 4; ++ni) {
                        int gl = (p * 64 + (wc & 1) * 32 + ni * 8) / GSIZE;
                        atomicAdd(&ssh[gl], js[ni]);
                        atomicAdd(&sqh[gl], jq[ni]);
                    }
                }
            }
            __syncthreads();
#pragma unroll
            for (int rr = 0; rr < 8; ++rr) {
                int r = w + rr * 8;
                int og = o0 + p * 64 + r;
                float4 v = *(float4*)&osf[r * 132 + lane * 4];
                if constexpr (EPI == EPI_FINAL) {
                    float* op = (float*)outv + ((size_t)b * O + og) * Nc + n0;
                    float bi = bias[og];
                    const float Minv = 1.f / (GSIZE * (float)Nc);
                    int gg = og / GSIZE;
                    float mean = gsum[b * 16 + gg] * Minv;
                    float var = fmaxf(gsq[b * 16 + gg] * Minv - mean * mean, 0.f);
                    float rstd = rsqrtf(var + 1e-6f);
                    float av = rstd * scgw[og];
                    float cv = scgb[og] - mean * av;
                    uint2 sraw = *(const uint2*)(scpre +
                        ((size_t)b * O + og) * Nc + n0 + lane * 4);
                    float2 s0 = __half22float2(*(__half2*)&sraw.x);
                    float2 s1 = __half22float2(*(__half2*)&sraw.y);
                    float ss[4] = {s0.x, s0.y, s1.x, s1.y};
                    float4 rrv;
#pragma unroll
                    for (int e = 0; e < 4; ++e) {
                        float x = (&v.x)[e] + bi + fmaf(ss[e], av, cv);
                        (&rrv.x)[e] = x > 0.f ? x : 0.01f * x;
                    }
                    *(float4*)(op + lane * 4) = rrv;
                } else {
                    __half* op = (__half*)outv + ((size_t)b * O + og) * Nc + n0;
                    uint2 st;
                    *(__half2*)&st.x = __floats2half2_rn(v.x, v.y);
                    *(__half2*)&st.y = __floats2half2_rn(v.z, v.w);
                    *(uint2*)(op + lane * 4) = st;
                }
            }
            __syncthreads();
        }
        if constexpr (EPI == EPI_TRANS_STATS) {
            constexpr int NG = 128 / GSIZE;
            if (tid < NG) {
                atomicAdd(&gsum[b * 16 + o0 / GSIZE + tid], ssh[tid]);
                atomicAdd(&gsq[b * 16 + o0 / GSIZE + tid], sqh[tid]);
            }
        }
    }
}

// ---------------- standalone conv kernels ----------------------------------
template <int O, int C, int EPI, int GSIZE>
__global__ __launch_bounds__(256, 2) void mma_conv_k(
    const __half* __restrict__ Wh, const float* __restrict__ bias,
    const __half* __restrict__ in, void* __restrict__ outv,
    const __half* __restrict__ scpre,
    const float* __restrict__ scgw, const float* __restrict__ scgb,
    float* gsum, float* gsq)
{
    extern __shared__ __align__(16) char smem[];
    conv_dev<O, C, EPI, GSIZE>(smem, blockIdx.x * 128, blockIdx.y * 128,
                               blockIdx.z, Wh, bias, in, outv,
                               scpre, scgw, scgb, gsum, gsq);
}

// ---------------- K2: mlp1 + shortcut conv + geo moments -------------------
__global__ __launch_bounds__(256, 2) void fused_a_kernel(
    const __half* __restrict__ wh, const float* __restrict__ b1,
    const float* __restrict__ sc_b, const __half* __restrict__ fT,
    __half* __restrict__ x1, __half* __restrict__ scp,
    float* scs, float* scq,
    const float* __restrict__ coords, const int* __restrict__ knn_idx,
    const float* __restrict__ knn_dist)
{
    extern __shared__ __align__(16) char smem[];
    int y = blockIdx.y, b = blockIdx.z;
    if (y == 5) {
        if (blockIdx.x < 64) geo_body(coords, knn_idx, knn_dist, blockIdx.x, b);
        return;
    }
    if (y == 0)
        conv_dev<128, 128, EPI_LEAKY02, 8>(smem, blockIdx.x * 128, 0, b,
            wh + WOFF_W1, b1, fT, x1, nullptr, nullptr, nullptr, nullptr, nullptr);
    else
        conv_dev<512, 128, EPI_TRANS_STATS, 32>(smem, blockIdx.x * 128,
            (y - 1) * 128, b, wh + WOFF_SC, sc_b, fT, scp,
            nullptr, nullptr, nullptr, scs, scq);
}

// ---------------- normalize p2 -> x3 with inline fin2 ----------------------
__global__ __launch_bounds__(256) void normalize_h_kernel(
    const __half* __restrict__ p, __half* __restrict__ x,
    const float* __restrict__ sums, const float* __restrict__ sqs,
    const float* __restrict__ gw, const float* __restrict__ gb)
{
    size_t i = ((size_t)blockIdx.x * blockDim.x + threadIdx.x) * 4;
    int c = (int)(i % 256);
    int b = (int)(i / ((size_t)Nc * 256));
    const float Minv = 1.f / (16.f * Nc);
    int g = c >> 4;
    float mean = sums[b * 16 + g] * Minv;
    float var = fmaxf(sqs[b * 16 + g] * Minv - mean * mean, 0.f);
    float rstd = rsqrtf(var + 1e-6f);
    __half2 v0 = *(const __half2*)(p + i);
    __half2 v1 = *(const __half2*)(p + i + 2);
    float vv[4] = {__half2float(v0.x), __half2float(v0.y),
                   __half2float(v1.x), __half2float(v1.y)};
    float rr[4];
#pragma unroll
    for (int e = 0; e < 4; ++e) {
        float a = rstd * gw[c + e];
        float cc = gb[c + e] - mean * a;
        rr[e] = fmaxf(fmaf(vv[e], a, cc), 0.f);
    }
    *(__half2*)(x + i) = __floats2half2_rn(rr[0], rr[1]);
    *(__half2*)(x + i + 2) = __floats2half2_rn(rr[2], rr[3]);
}

// ---------------- K4: BOTH geo layers + lse1 gather (shared setup) ----------
static constexpr int PTS = 8;
__global__ __launch_bounds__(128) void lse_geo12_kernel(
    const float* __restrict__ coords, const int* __restrict__ knn_idx,
    const float* __restrict__ knn_dist,
    const float4* __restrict__ lw1, const float4* __restrict__ lw2,
    const __half* __restrict__ xsrc,
    __half* __restrict__ m1, __half* __restrict__ m2)
{
    __shared__ int sh_off[128];
    __shared__ float4 sh_g[128];
    __shared__ float sh_ctr[PTS][3];
    __shared__ float2 spart[PTS][64];

    const int b = blockIdx.y;
    const int n0 = blockIdx.x * PTS;
    const int tid = threadIdx.x;
    const float* cb = coords + (size_t)b * Nc * 3;

    size_t base = ((size_t)b * Nc + n0) * 16 + tid;
    const int jv = knn_idx[base];
    const float ddv = knn_dist[base];
    sh_off[tid] = jv << 8;
    if (tid < PTS * 3) sh_ctr[tid / 3][tid % 3] = cb[n0 * 3 + tid];
    __syncthreads();
    sh_g[tid] = make_float4(cb[jv * 3 + 0], cb[jv * 3 + 1], cb[jv * 3 + 2], ddv);

    const float4 f0a = lw1[(b * 128 + tid) * 2 + 0];
    const float4 f1a = lw1[(b * 128 + tid) * 2 + 1];
    const float4 f0b = lw2[(b * 128 + tid) * 2 + 0];
    const float4 f1b = lw2[(b * 128 + tid) * 2 + 1];

    const int cp = tid & 63, h = tid >> 6;
    const char* xbp = (const char*)(xsrc + (size_t)b * Nc * 128) + 4 * cp;
    __half* mo1 = m1 + ((size_t)b * Nc + n0) * 256;
    __half* mo2 = m2 + ((size_t)b * Nc + n0) * 256;
    __syncthreads();

    float2 accn[PTS];
#pragma unroll
    for (int pi = 0; pi < PTS; pi++) {
        float dotcA = fmaf(f0a.x, sh_ctr[pi][0],
                      fmaf(f0a.y, sh_ctr[pi][1],
                      fmaf(f0a.z, sh_ctr[pi][2], f0a.w)));
        float dotcB = fmaf(f0b.x, sh_ctr[pi][0],
                      fmaf(f0b.y, sh_ctr[pi][1],
                      fmaf(f0b.z, sh_ctr[pi][2], f0b.w)));
        float accA = 0.f, accB = 0.f;
#pragma unroll
        for (int k = 0; k < 16; k++) {
            float4 gv = sh_g[pi * 16 + k];
            float dA = fmaf(f1a.x, gv.x, fmaf(f1a.y, gv.y,
                       fmaf(f1a.z, gv.z, fmaf(f1a.w, gv.w, dotcA))));
            float dB = fmaf(f1b.x, gv.x, fmaf(f1b.y, gv.y,
                       fmaf(f1b.z, gv.z, fmaf(f1b.w, gv.w, dotcB))));
            accA += fmaxf(dA, 0.f);
            accB += fmaxf(dB, 0.f);
        }
        mo1[(size_t)pi * 256 + tid] = __float2half(accA * 0.0625f);
        mo2[(size_t)pi * 256 + tid] = __float2half(accB * 0.0625f);

        // lse1 gather (x1, no affine)
        float2 acc = make_float2(0.f, 0.f);
        const int sb0 = pi * 16 + h * 8;
#pragma unroll
        for (int k = 0; k < 8; k++) {
            int off = sh_off[sb0 + k];
            float2 f = __half22float2(*(const __half2*)(xbp + off));
            acc.x += f.x; acc.y += f.y;
        }
        if (h == 1) spart[pi][cp] = acc;
        accn[pi] = acc;
    }
    __syncthreads();
    if (h == 0) {
#pragma unroll
        for (int pi = 0; pi < PTS; pi++) {
            float2 o = spart[pi][cp];
            o.x = (o.x + accn[pi].x) * 0.0625f;
            o.y = (o.y + accn[pi].y) * 0.0625f;
            *(__half2*)&mo1[(size_t)pi * 256 + 128 + 2 * cp] =
                __floats2half2_rn(o.x, o.y);
        }
    }
}

// ---------------- K6: lse2 gather only (inline pool1 GN) --------------------
__global__ __launch_bounds__(128) void lse_gather2_kernel(
    const int* __restrict__ knn_idx, const __half* __restrict__ p1,
    __half* __restrict__ m2,
    const float* __restrict__ sums, const float* __restrict__ sqs,
    const float* __restrict__ pgw, const float* __restrict__ pgb)
{
    __shared__ int sh_off[128];
    __shared__ float2 spart[PTS][64];

    const int b = blockIdx.y;
    const int n0 = blockIdx.x * PTS;
    const int tid = threadIdx.x;

    size_t base = ((size_t)b * Nc + n0) * 16 + tid;
    sh_off[tid] = knn_idx[base] << 8;

    const int cp = tid & 63, h = tid >> 6;
    const float Minv = 1.f / (8.f * Nc);
    int ch0 = 2 * cp;
    int g = ch0 >> 3;
    float mean = sums[b * 16 + g] * Minv;
    float var = fmaxf(sqs[b * 16 + g] * Minv - mean * mean, 0.f);
    float rstd = rsqrtf(var + 1e-6f);
    float an0 = rstd * pgw[ch0];
    float cn0 = pgb[ch0] - mean * an0;
    float an1 = rstd * pgw[ch0 + 1];
    float cn1 = pgb[ch0 + 1] - mean * an1;

    const char* xbp = (const char*)(p1 + (size_t)b * Nc * 128) + 4 * cp;
    __half* mo = m2 + ((size_t)b * Nc + n0) * 256;
    __syncthreads();

    float2 accn[PTS];
#pragma unroll
    for (int pi = 0; pi < PTS; pi++) {
        float2 acc = make_float2(0.f, 0.f);
        const int sb0 = pi * 16 + h * 8;
#pragma unroll
        for (int k = 0; k < 8; k++) {
            int off = sh_off[sb0 + k];
            float2 f = __half22float2(*(const __half2*)(xbp + off));
            f.x = fmaxf(fmaf(f.x, an0, cn0), 0.f);
            f.y = fmaxf(fmaf(f.y, an1, cn1), 0.f);
            acc.x += f.x; acc.y += f.y;
        }
        if (h == 1) spart[pi][cp] = acc;
        accn[pi] = acc;
    }
    __syncthreads();
    if (h == 0) {
#pragma unroll
        for (int pi = 0; pi < PTS; pi++) {
            float2 o = spart[pi][cp];
            o.x = (o.x + accn[pi].x) * 0.0625f;
            o.y = (o.y + accn[pi].y) * 0.0625f;
            *(__half2*)&mo[(size_t)pi * 256 + 128 + 2 * cp] =
                __floats2half2_rn(o.x, o.y);
        }
    }
}

// ---------------- host ----------------
#define SYM(ty, p, s) do { void* _t; cudaGetSymbolAddress(&_t, s); p = (ty)_t; } while (0)

extern "C" void kernel_launch(void* const* d_in, const int* in_sizes, int n_in,
                              void* d_out, int out_size)
{
    (void)in_sizes; (void)n_in; (void)out_size;
    const float* coords   = (const float*)d_in[0];
    const float* features = (const float*)d_in[1];
    const float* knn_dist = (const float*)d_in[2];
    const int*   knn_idx  = (const int*)d_in[3];
    const float* w1       = (const float*)d_in[4];
    const float* b1       = (const float*)d_in[5];
    const float* lse1_w   = (const float*)d_in[6];
    const float* lse1_b   = (const float*)d_in[7];
    const float* lse1_gw  = (const float*)d_in[8];
    const float* lse1_gb  = (const float*)d_in[9];
    const float* pool1_w  = (const float*)d_in[10];
    const float* pool1_b  = (const float*)d_in[11];
    const float* pool1_gw = (const float*)d_in[12];
    const float* pool1_gb = (const float*)d_in[13];
    const float* lse2_w   = (const float*)d_in[14];
    const float* lse2_b   = (const float*)d_in[15];
    const float* lse2_gw  = (const float*)d_in[16];
    const float* lse2_gb  = (const float*)d_in[17];
    const float* pool2_w  = (const float*)d_in[18];
    const float* pool2_b  = (const float*)d_in[19];
    const float* pool2_gw = (const float*)d_in[20];
    const float* pool2_gb = (const float*)d_in[21];
    const float* mlp2_w   = (const float*)d_in[22];
    const float* mlp2_b   = (const float*)d_in[23];
    const float* sc_w     = (const float*)d_in[24];
    const float* sc_b     = (const float*)d_in[25];
    const float* sc_gw    = (const float*)d_in[26];
    const float* sc_gb    = (const float*)d_in[27];
    float* out = (float*)d_out;

    __half *fT, *wh, *x1, *m1, *p1, *m2, *p2, *x3, *scp;
    float4 *lw1, *lw2;
    float *p1s, *p1q, *p2s, *p2q, *scs, *scq;
    SYM(__half*, fT, g_fT); SYM(__half*, wh, g_wh);
    SYM(__half*, x1, g_x1); SYM(__half*, m1, g_m1); SYM(__half*, p1, g_p1);
    SYM(__half*, m2, g_m2); SYM(__half*, p2, g_p2); SYM(__half*, x3, g_x3);
    SYM(__half*, scp, g_scp);
    SYM(float4*, lw1, g_lw1); SYM(float4*, lw2, g_lw2);
    SYM(float*, p1s, g_p1s); SYM(float*, p1q, g_p1q);
    SYM(float*, p2s, g_p2s); SYM(float*, p2q, g_p2q);
    SYM(float*, scs, g_scs); SYM(float*, scq, g_scq);

    cudaFuncSetAttribute(fused_a_kernel,
                         cudaFuncAttributeMaxDynamicSharedMemorySize, CONV_SMEM);
    cudaFuncSetAttribute(mma_conv_k<128, 256, EPI_STATS, 8>,
                         cudaFuncAttributeMaxDynamicSharedMemorySize, CONV_SMEM);
    cudaFuncSetAttribute(mma_conv_k<256, 256, EPI_STATS, 16>,
                         cudaFuncAttributeMaxDynamicSharedMemorySize, CONV_SMEM);
    cudaFuncSetAttribute(mma_conv_k<512, 256, EPI_FINAL, 32>,
                         cudaFuncAttributeMaxDynamicSharedMemorySize, CONV_SMEM);

    // K1: zero stats + weight convert + feature transpose
    prep_transpose_kernel<<<4096 + 256, 256>>>(w1, pool1_w, pool2_w, sc_w,
                                               mlp2_w, features, fT);
    // K2: mlp1 (y=0) + shortcut conv (y=1..4) + geo moments (y=5)
    fused_a_kernel<<<dim3(Nc / 128, 6, Bc), 256, CONV_SMEM>>>(
        wh, b1, sc_b, fT, x1, scp, scs, scq, coords, knn_idx, knn_dist);
    // K3: closed-form GN for both LSE layers -> prefolded weights
    lse_finalize_kernel<<<dim3(Bc, 2), 128>>>(lse1_w, lse1_b, lse1_gw, lse1_gb,
                                              lse2_w, lse2_b, lse2_gw, lse2_gb);
    // K4: geo for BOTH layers + lse1 gather
    lse_geo12_kernel<<<dim3(Nc / PTS, Bc), 128>>>(
        coords, knn_idx, knn_dist, lw1, lw2, x1, m1, m2);
    // K5: pool1 conv + stats
    mma_conv_k<128, 256, EPI_STATS, 8>
        <<<dim3(Nc / 128, 1, Bc), 256, CONV_SMEM>>>(wh + WOFF_P1, pool1_b, m1, p1,
                                                    nullptr, nullptr, nullptr,
                                                    p1s, p1q);
    // K6: lse2 gather only (inline pool1 GN finalize)
    lse_gather2_kernel<<<dim3(Nc / PTS, Bc), 128>>>(
        knn_idx, p1, m2, p1s, p1q, pool1_gw, pool1_gb);
    // K7: pool2 conv + stats
    mma_conv_k<256, 256, EPI_STATS, 16>
        <<<dim3(Nc / 128, 2, Bc), 256, CONV_SMEM>>>(wh + WOFF_P2, pool2_b, m2, p2,
                                                    nullptr, nullptr, nullptr,
                                                    p2s, p2q);
    // K8: normalize (inline pool2 GN finalize)
    normalize_h_kernel<<<(Bc * Nc * 256) / 1024, 256>>>(p2, x3, p2s, p2q,
                                                        pool2_gw, pool2_gb);
    // K9: final conv + inline shortcut GN + leaky(0.01) -> out [b][o][n] fp32
    mma_conv_k<512, 256, EPI_FINAL, 32>
        <<<dim3(Nc / 128, 4, Bc), 256, CONV_SMEM>>>(wh + WOFF_M2, mlp2_b, x3, out,
                                                    scp, sc_gw, sc_gb, scs, scq);
}